// round 11
// baseline (speedup 1.0000x reference)
#include <cuda_runtime.h>
#include <cuda_fp16.h>
#include <cstdint>
#include <math.h>

// Problem constants
#define BB 2
#define TT 2048
#define EE 1024
#define HH 16
#define DD 64
#define VV 32000
#define BT (BB * TT)   // 4096

// ---------------- scratch (device globals; no allocations allowed) ------------
__device__ __half g_xh[BT * EE];
__device__ __half g_oh[BT * EE];
__device__ __half g_wqh[EE * EE];
__device__ __half g_wkh[EE * EE];
__device__ __half g_wvh[EE * EE];
__device__ __half g_woh[VV * EE];
__device__ float g_q[BT * EE];
__device__ float g_k[BT * EE];
__device__ float g_v[BT * EE];
__device__ float g_lterms[BT];

// ---------------- asm helpers --------------------------------------------------
__device__ __forceinline__ uint32_t smem_u32(const void* p) {
    uint32_t a;
    asm("{ .reg .u64 t; cvta.to.shared.u64 t, %1; cvt.u32.u64 %0, t; }" : "=r"(a) : "l"(p));
    return a;
}

__device__ __forceinline__ void cp_async16(uint32_t dst, const void* src) {
    asm volatile("cp.async.cg.shared.global [%0], [%1], 16;" :: "r"(dst), "l"(src));
}
__device__ __forceinline__ void cp_commit() {
    asm volatile("cp.async.commit_group;");
}
template <int N>
__device__ __forceinline__ void cp_wait() {
    asm volatile("cp.async.wait_group %0;" :: "n"(N));
}

__device__ __forceinline__ uint4 ldsm_x4(uint32_t addr) {
    uint4 r;
    asm volatile("ldmatrix.sync.aligned.m8n8.x4.shared.b16 {%0,%1,%2,%3}, [%4];"
                 : "=r"(r.x), "=r"(r.y), "=r"(r.z), "=r"(r.w) : "r"(addr));
    return r;
}

// fp16 m16n8k16, fp32 accumulate
__device__ __forceinline__ void mma_f16(float* d, const uint4& a, uint32_t b0, uint32_t b1) {
    asm volatile(
        "mma.sync.aligned.m16n8k16.row.col.f32.f16.f16.f32 "
        "{%0,%1,%2,%3}, {%4,%5,%6,%7}, {%8,%9}, {%0,%1,%2,%3};"
        : "+f"(d[0]), "+f"(d[1]), "+f"(d[2]), "+f"(d[3])
        : "r"(a.x), "r"(a.y), "r"(a.z), "r"(a.w), "r"(b0), "r"(b1));
}

// ---------------- embedding: xh = half(tok_table[tokens] + pos_emb) -----------
__global__ void embed_kernel(const int* __restrict__ tokens,
                             const float* __restrict__ tok_table,
                             const float* __restrict__ pos_emb,
                             __half* __restrict__ xh) {
    int i4 = blockIdx.x * blockDim.x + threadIdx.x;   // over BT*EE/4
    int bt = i4 >> 8;                                  // /(EE/4)
    int e4 = i4 & 255;
    int t = bt & (TT - 1);
    int tok = tokens[bt];
    float4 a = *(const float4*)(tok_table + (size_t)tok * EE + e4 * 4);
    float4 p = *(const float4*)(pos_emb + (size_t)t * EE + e4 * 4);
    __half2 h0 = __floats2half2_rn(a.x + p.x, a.y + p.y);
    __half2 h1 = __floats2half2_rn(a.z + p.z, a.w + p.w);
    *(__half2*)(xh + (size_t)i4 * 4) = h0;
    *(__half2*)(xh + (size_t)i4 * 4 + 2) = h1;
}

// ---------------- fp32 -> fp16 convert (weights, one-shot) --------------------
__global__ void cvt_f2h(const float* __restrict__ src, __half* __restrict__ dst) {
    int i = blockIdx.x * blockDim.x + threadIdx.x;    // over n/4
    float4 v = ((const float4*)src)[i];
    __half2 h0 = __floats2half2_rn(v.x, v.y);
    __half2 h1 = __floats2half2_rn(v.z, v.w);
    ((__half2*)dst)[i * 2] = h0;
    ((__half2*)dst)[i * 2 + 1] = h1;
}

// ====== cp.async + ldmatrix fp16 NT GEMM: C = A B^T + bias ====================
// CTA tile 128x128, BK=64 (4 k16-steps). 256 threads, 8 warps (2x4),
// warp tile 64x32. 3-stage cp.async ring. SW128 swizzle (128B rows, 3-bit XOR).
// smem per stage: A 128x64h = 16KB, B 16KB. Total 96KB dynamic.

#define GM_BM 128
#define GM_BN 128
#define GM_BK 64
#define GM_STAGE_BYTES 32768
#define GSM_BYTES (3 * GM_STAGE_BYTES)

__device__ __forceinline__ void gm_copy_tile(uint32_t sdst, const __half* __restrict__ G,
                                             int K, int k0, int tid) {
    // 128 rows x 8 chunks of 16B (8 halfs); swizzle chunk ^ (row&7)
#pragma unroll
    for (int it = 0; it < 4; it++) {
        int q = tid + it * 256;
        int row = q >> 3, c = q & 7;
        uint32_t dst = sdst + row * 128 + ((c ^ (row & 7)) << 4);
        cp_async16(dst, G + (size_t)row * K + k0 + c * 8);
    }
}

__global__ __launch_bounds__(256, 2) void gemm_h(const __half* __restrict__ A,
                                                 const __half* __restrict__ B,
                                                 const float* __restrict__ bias,
                                                 float* __restrict__ C,
                                                 int M, int N, int K) {
    extern __shared__ __half sm[];
    uint32_t sbase = smem_u32(sm);

    int tid = threadIdx.x;
    int lane = tid & 31, wid = tid >> 5;
    int warp_m = wid >> 2, warp_n = wid & 3;
    int g = lane >> 2, t = lane & 3;

    int bm = blockIdx.x * GM_BM;
    int bn = blockIdx.y * GM_BN;

    const __half* Ag = A + (size_t)bm * K;
    const __half* Bg = B + (size_t)bn * K;

    float acc[4][4][4];
#pragma unroll
    for (int mi = 0; mi < 4; mi++)
#pragma unroll
        for (int ni = 0; ni < 4; ni++)
#pragma unroll
            for (int e = 0; e < 4; e++) acc[mi][ni][e] = 0.0f;

    const int NCH = K / GM_BK;    // 16 for K=1024

    // per-lane ldmatrix row/col geometry
    int a_row = (lane & 7) + ((lane >> 3) & 1) * 8;   // row within 16-row block
    int a_col = lane >> 4;                            // k16-half chunk select
    int a_r7 = a_row & 7;
    int b_row = (lane & 7) + (lane >> 4) * 8;         // row within 16-n block
    int b_col = (lane >> 3) & 1;
    int b_r7 = b_row & 7;
    int am_base = warp_m * 64 + a_row;                // A smem row for mi=0
    int bn_base = warp_n * 32 + b_row;                // B smem row for pair p=0

    // prologue: stages 0 and 1 in flight
    gm_copy_tile(sbase, Ag, K, 0, tid);
    gm_copy_tile(sbase + 16384, Bg, K, 0, tid);
    cp_commit();
    gm_copy_tile(sbase + GM_STAGE_BYTES, Ag, K, GM_BK, tid);
    gm_copy_tile(sbase + GM_STAGE_BYTES + 16384, Bg, K, GM_BK, tid);
    cp_commit();

    int sidx = 0;          // stage of current compute
    for (int i = 0; i < NCH; i++) {
        if (i + 1 < NCH) cp_wait<1>(); else cp_wait<0>();
        __syncthreads();

        // issue stage i+2 (buffer (i+2)%3 was consumed at iter i-1)
        if (i + 2 < NCH) {
            int ws = sidx + 2; if (ws >= 3) ws -= 3;
            uint32_t wb = sbase + ws * GM_STAGE_BYTES;
            gm_copy_tile(wb, Ag, K, (i + 2) * GM_BK, tid);
            gm_copy_tile(wb + 16384, Bg, K, (i + 2) * GM_BK, tid);
            cp_commit();
        }

        uint32_t Ab = sbase + sidx * GM_STAGE_BYTES;
        uint32_t Bb = Ab + 16384;

#pragma unroll
        for (int ks = 0; ks < 4; ks++) {
            uint4 af[4];
            uint4 bq[2];
            int akc = ((ks * 2 + a_col) ^ a_r7) << 4;
            int bkc = ((ks * 2 + b_col) ^ b_r7) << 4;
#pragma unroll
            for (int mi = 0; mi < 4; mi++)
                af[mi] = ldsm_x4(Ab + (am_base + mi * 16) * 128 + akc);
#pragma unroll
            for (int p = 0; p < 2; p++)
                bq[p] = ldsm_x4(Bb + (bn_base + p * 16) * 128 + bkc);
#pragma unroll
            for (int mi = 0; mi < 4; mi++) {
                mma_f16(acc[mi][0], af[mi], bq[0].x, bq[0].y);
                mma_f16(acc[mi][1], af[mi], bq[0].z, bq[0].w);
                mma_f16(acc[mi][2], af[mi], bq[1].x, bq[1].y);
                mma_f16(acc[mi][3], af[mi], bq[1].z, bq[1].w);
            }
        }
        __syncthreads();
        sidx++; if (sidx >= 3) sidx = 0;
    }

    // epilogue: add bias, store
    int m_base = bm + warp_m * 64;
    int n_base = bn + warp_n * 32;
#pragma unroll
    for (int mi = 0; mi < 4; mi++) {
#pragma unroll
        for (int ni = 0; ni < 4; ni++) {
            int r0 = m_base + mi * 16 + g;
            int col = n_base + ni * 8 + t * 2;
            float b0 = __ldg(&bias[col]);
            float b1 = __ldg(&bias[col + 1]);
            float2 o0 = make_float2(acc[mi][ni][0] + b0, acc[mi][ni][1] + b1);
            float2 o1 = make_float2(acc[mi][ni][2] + b0, acc[mi][ni][3] + b1);
            *(float2*)&C[(size_t)r0 * N + col] = o0;
            *(float2*)&C[(size_t)(r0 + 8) * N + col] = o1;
        }
    }
}

// ---------------- causal attention (flash-style, online softmax) --------------
#define AT_TQ 16
#define AT_TS 64

__global__ __launch_bounds__(256) void attn_kernel(const float* __restrict__ q,
                                                   const float* __restrict__ k,
                                                   const float* __restrict__ v,
                                                   __half* __restrict__ oh) {
    int qt0 = blockIdx.x * AT_TQ;
    int h = blockIdx.y;
    int b = blockIdx.z;

    __shared__ float Qs[AT_TQ][DD + 1];
    __shared__ float Ks[AT_TS][DD + 1];
    __shared__ float Vs[AT_TS][DD + 1];
    __shared__ float Ps[AT_TQ][AT_TS + 1];
    __shared__ float m_s[AT_TQ], l_s[AT_TQ], alpha_s[AT_TQ];

    int tid = threadIdx.x;

    for (int i = tid; i < AT_TQ * DD; i += 256) {
        int r = i >> 6, d = i & 63;
        Qs[r][d] = q[(size_t)(b * TT + qt0 + r) * EE + h * DD + d];
    }
    if (tid < AT_TQ) { m_s[tid] = -1e30f; l_s[tid] = 0.0f; }
    __syncthreads();

    float o_acc[4] = {0.f, 0.f, 0.f, 0.f};
    int d_own = tid & 63;
    int r_base = (tid >> 6) * 4;

    int n_tiles = (qt0 + AT_TQ - 1) / AT_TS + 1;

    for (int kt = 0; kt < n_tiles; kt++) {
        int s0 = kt * AT_TS;
        for (int i = tid; i < AT_TS * DD; i += 256) {
            int r = i >> 6, d = i & 63;
            size_t gi = (size_t)(b * TT + s0 + r) * EE + h * DD + d;
            Ks[r][d] = k[gi];
            Vs[r][d] = v[gi];
        }
        __syncthreads();

        float sacc[4] = {0.f, 0.f, 0.f, 0.f};
#pragma unroll
        for (int d = 0; d < DD; d++) {
            float kv = Ks[d_own][d];
#pragma unroll
            for (int j = 0; j < 4; j++) sacc[j] = fmaf(Qs[r_base + j][d], kv, sacc[j]);
        }
        int s_glob = s0 + d_own;
#pragma unroll
        for (int j = 0; j < 4; j++) {
            int t_glob = qt0 + r_base + j;
            Ps[r_base + j][d_own] = (s_glob <= t_glob) ? sacc[j] : -1e30f;
        }
        __syncthreads();

        int warp = tid >> 5, lane = tid & 31;
#pragma unroll
        for (int rw = 0; rw < 2; rw++) {
            int rr = warp * 2 + rw;
            float x0 = Ps[rr][lane], x1 = Ps[rr][lane + 32];
            float mx = fmaxf(x0, x1);
#pragma unroll
            for (int off = 16; off; off >>= 1)
                mx = fmaxf(mx, __shfl_xor_sync(0xffffffffu, mx, off));
            float m_old = m_s[rr];
            float m_new = fmaxf(m_old, mx);
            float e0 = __expf(x0 - m_new);
            float e1 = __expf(x1 - m_new);
            float sum = e0 + e1;
#pragma unroll
            for (int off = 16; off; off >>= 1)
                sum += __shfl_xor_sync(0xffffffffu, sum, off);
            Ps[rr][lane] = e0;
            Ps[rr][lane + 32] = e1;
            if (lane == 0) {
                float alpha = __expf(m_old - m_new);
                alpha_s[rr] = alpha;
                l_s[rr] = l_s[rr] * alpha + sum;
                m_s[rr] = m_new;
            }
        }
        __syncthreads();

#pragma unroll
        for (int j = 0; j < 4; j++) o_acc[j] *= alpha_s[r_base + j];
#pragma unroll
        for (int s = 0; s < AT_TS; s++) {
            float vv = Vs[s][d_own];
#pragma unroll
            for (int j = 0; j < 4; j++) o_acc[j] = fmaf(Ps[r_base + j][s], vv, o_acc[j]);
        }
        __syncthreads();
    }

#pragma unroll
    for (int j = 0; j < 4; j++) {
        int r = r_base + j;
        oh[(size_t)(b * TT + qt0 + r) * EE + h * DD + d_own] =
            __float2half(o_acc[j] / l_s[r] * 0.125f);
    }
}

// ---------------- per-row logsumexp + per-row loss term -----------------------
__global__ __launch_bounds__(256) void lse_loss_kernel(const float* __restrict__ logits,
                                                       const int* __restrict__ targets,
                                                       float* __restrict__ lterms) {
    int row = blockIdx.x;
    const float* p = logits + (size_t)row * VV;
    float m = -1e30f, l = 0.0f;
    for (int i = threadIdx.x; i < VV; i += 256) {
        float x = p[i];
        if (x > m) { l = l * __expf(m - x) + 1.0f; m = x; }
        else       { l += __expf(x - m); }
    }
    __shared__ float ms[256], ls[256];
    ms[threadIdx.x] = m;
    ls[threadIdx.x] = l;
    __syncthreads();
    for (int s = 128; s; s >>= 1) {
        if (threadIdx.x < (unsigned)s) {
            float m2 = ms[threadIdx.x + s], l2 = ls[threadIdx.x + s];
            float M = fmaxf(ms[threadIdx.x], m2);
            ls[threadIdx.x] = ls[threadIdx.x] * __expf(ms[threadIdx.x] - M) + l2 * __expf(m2 - M);
            ms[threadIdx.x] = M;
        }
        __syncthreads();
    }
    if (threadIdx.x == 0) {
        float lse = ms[0] + logf(ls[0]);
        lterms[row] = lse - p[targets[row]];
    }
}

__global__ __launch_bounds__(256) void loss_reduce(const float* __restrict__ lterms,
                                                   float* __restrict__ out, int do_write) {
    __shared__ float s[256];
    float acc = 0.0f;
    for (int i = threadIdx.x; i < BT; i += 256) acc += lterms[i];
    s[threadIdx.x] = acc;
    __syncthreads();
    for (int st = 128; st; st >>= 1) {
        if (threadIdx.x < (unsigned)st) s[threadIdx.x] += s[threadIdx.x + st];
        __syncthreads();
    }
    if (threadIdx.x == 0 && do_write) out[0] = s[0] / (float)BT;
}

// ------------------------------- launch ---------------------------------------
extern "C" void kernel_launch(void* const* d_in, const int* in_sizes, int n_in,
                              void* d_out, int out_size) {
    const int*   tokens    = (const int*)d_in[0];
    const int*   targets   = (const int*)d_in[1];
    const float* tok_table = (const float*)d_in[2];
    const float* pos_emb   = (const float*)d_in[3];
    const float* Wq        = (const float*)d_in[4];
    const float* bq        = (const float*)d_in[5];
    const float* Wk        = (const float*)d_in[6];
    const float* bk        = (const float*)d_in[7];
    const float* Wv        = (const float*)d_in[8];
    const float* bv        = (const float*)d_in[9];
    const float* Wo        = (const float*)d_in[10];
    const float* bo        = (const float*)d_in[11];
    float* out = (float*)d_out;

    __half *xh, *oh, *wqh, *wkh, *wvh, *woh;
    float *q, *k, *v, *lt;
    cudaGetSymbolAddress((void**)&xh,  g_xh);
    cudaGetSymbolAddress((void**)&oh,  g_oh);
    cudaGetSymbolAddress((void**)&wqh, g_wqh);
    cudaGetSymbolAddress((void**)&wkh, g_wkh);
    cudaGetSymbolAddress((void**)&wvh, g_wvh);
    cudaGetSymbolAddress((void**)&woh, g_woh);
    cudaGetSymbolAddress((void**)&q,   g_q);
    cudaGetSymbolAddress((void**)&k,   g_k);
    cudaGetSymbolAddress((void**)&v,   g_v);
    cudaGetSymbolAddress((void**)&lt,  g_lterms);

    static int smem_set = 0;
    if (!smem_set) {
        cudaFuncSetAttribute(gemm_h, cudaFuncAttributeMaxDynamicSharedMemorySize,
                             (int)GSM_BYTES);
        smem_set = 1;
    }

    // 1) embedding (fp16) + one-shot weight converts
    embed_kernel<<<(BT * EE / 4) / 256, 256>>>(tokens, tok_table, pos_emb, xh);
    cvt_f2h<<<(EE * EE / 4) / 256, 256>>>(Wq, wqh);
    cvt_f2h<<<(EE * EE / 4) / 256, 256>>>(Wk, wkh);
    cvt_f2h<<<(EE * EE / 4) / 256, 256>>>(Wv, wvh);
    cvt_f2h<<<(VV * EE / 4) / 256, 256>>>(Wo, woh);

    // 2) QKV projections
    dim3 gqkv(BT / GM_BM, EE / GM_BN);
    gemm_h<<<gqkv, 256, GSM_BYTES>>>(xh, wqh, bq, q, BT, EE, EE);
    gemm_h<<<gqkv, 256, GSM_BYTES>>>(xh, wkh, bk, k, BT, EE, EE);
    gemm_h<<<gqkv, 256, GSM_BYTES>>>(xh, wvh, bv, v, BT, EE, EE);

    // 3) causal attention -> fp16 O
    attn_kernel<<<dim3(TT / AT_TQ, HH, BB), 256>>>(q, k, v, oh);

    // 4) output projection -> logits into d_out
    dim3 glog(BT / GM_BM, VV / GM_BN);
    gemm_h<<<glog, 256, GSM_BYTES>>>(oh, woh, bo, out, BT, VV, EE);

    // 5) loss
    lse_loss_kernel<<<BT, 256>>>(out, targets, lt);
    int write_loss = (out_size > BT * VV) ? 1 : 0;
    loss_reduce<<<1, 256>>>(lt, out + (size_t)BT * VV, write_loss);
}

// round 13
// speedup vs baseline: 1.0924x; 1.0924x over previous
#include <cuda_runtime.h>
#include <cuda_fp16.h>
#include <cstdint>
#include <math.h>

// Problem constants
#define BB 2
#define TT 2048
#define EE 1024
#define HH 16
#define DD 64
#define VV 32000
#define BT (BB * TT)   // 4096

// ---------------- scratch (device globals; no allocations allowed) ------------
__device__ __half g_xh[BT * EE];
__device__ __half g_oh[BT * EE];
__device__ __half g_wqh[EE * EE];
__device__ __half g_wkh[EE * EE];
__device__ __half g_wvh[EE * EE];
__device__ __half g_woh[(size_t)VV * EE];
__device__ float g_q[BT * EE];
__device__ float g_k[BT * EE];
__device__ float g_v[BT * EE];
__device__ float g_lterms[BT];

// ---------------- helpers -----------------------------------------------------
// fp16 m16n8k16, fp32 accumulate
__device__ __forceinline__ void mma_f16(float* d, const uint4& a, const uint2& b) {
    asm volatile(
        "mma.sync.aligned.m16n8k16.row.col.f32.f16.f16.f32 "
        "{%0,%1,%2,%3}, {%4,%5,%6,%7}, {%8,%9}, {%0,%1,%2,%3};"
        : "+f"(d[0]), "+f"(d[1]), "+f"(d[2]), "+f"(d[3])
        : "r"(a.x), "r"(a.y), "r"(a.z), "r"(a.w), "r"(b.x), "r"(b.y));
}

// ---------------- embedding: xh = half(tok_table[tokens] + pos_emb) -----------
__global__ void embed_kernel(const int* __restrict__ tokens,
                             const float* __restrict__ tok_table,
                             const float* __restrict__ pos_emb,
                             __half* __restrict__ xh) {
    int i4 = blockIdx.x * blockDim.x + threadIdx.x;   // over BT*EE/4
    int bt = i4 >> 8;                                  // /(EE/4)
    int e4 = i4 & 255;
    int t = bt & (TT - 1);
    int tok = tokens[bt];
    float4 a = *(const float4*)(tok_table + (size_t)tok * EE + e4 * 4);
    float4 p = *(const float4*)(pos_emb + (size_t)t * EE + e4 * 4);
    __half2 h0 = __floats2half2_rn(a.x + p.x, a.y + p.y);
    __half2 h1 = __floats2half2_rn(a.z + p.z, a.w + p.w);
    *(__half2*)(xh + (size_t)i4 * 4) = h0;
    *(__half2*)(xh + (size_t)i4 * 4 + 2) = h1;
}

// ---------------- fp32 -> fp16 convert (weights, one-shot) --------------------
__global__ void cvt_f2h(const float* __restrict__ src, __half* __restrict__ dst) {
    size_t i = (size_t)blockIdx.x * blockDim.x + threadIdx.x;    // over n/4
    float4 v = ((const float4*)src)[i];
    __half2 h0 = __floats2half2_rn(v.x, v.y);
    __half2 h1 = __floats2half2_rn(v.z, v.w);
    ((__half2*)dst)[i * 2] = h0;
    ((__half2*)dst)[i * 2 + 1] = h1;
}

// ====== mma.sync fp16 NT GEMM (R9 mainloop, fp16 gmem operands) ===============
// CTA tile 128x128, BK=32 (2 k-steps of 16). 256 threads, 8 warps (2x4),
// warp tile 64x32 = 4x4 m16n8k16 fragments. fp32 accumulate. 2 CTAs/SM.
//
// SMEM (fragment-native uint32 arrays, conflict pattern identical to R9):
//   As: [R=8 (16-row blk)][ks=2][lane=32][4]   (2048 u32 = 8KB per buffer)
//   Bs: [Nb=16 (8-col blk)][ks=2][lane=32][2]  (2048 u32 = 8KB per buffer)
// Loader: chunk = 128 rows x 32 halfs; per thread 2 x LDG.128 (8 halfs each),
// scattered as 4 packed u32 per load (no conversion in-loop).

#define GM_BM 128
#define GM_BN 128
#define GM_BK 32
#define GM_BUF 2048     // uint32 per As or Bs buffer

__device__ __forceinline__ void gm_ldg(const __half* __restrict__ P, int K, int k0,
                                       int tid, uint4* p) {
#pragma unroll
    for (int it = 0; it < 2; it++) {
        int q = tid + it * 256;          // 0..511
        int row = q >> 2, c = q & 3;     // 4 x 16B chunks per 64B row
        p[it] = *(const uint4*)(P + (size_t)row * K + k0 + c * 8);
    }
}

__device__ __forceinline__ void gm_stA(uint32_t* __restrict__ As, const uint4* p, int tid) {
#pragma unroll
    for (int it = 0; it < 2; it++) {
        int q = tid + it * 256;
        int row = q >> 2, c = q & 3;
        int ks = c >> 1;                 // k16 step
        int kk = (c & 1) << 3;           // 0 or 8 within k16
        int R = row >> 4, r16 = row & 15;
        int g = r16 & 7, hi = r16 >> 3;
        int reg = (kk >> 3) * 2 + hi;    // 0/1 (k<8) or 2/3 (k>=8)
        int base = (R * 2 + ks) * 32 + g * 4;
        const uint32_t* w = (const uint32_t*)&p[it];
        As[(base + 0) * 4 + reg] = w[0];
        As[(base + 1) * 4 + reg] = w[1];
        As[(base + 2) * 4 + reg] = w[2];
        As[(base + 3) * 4 + reg] = w[3];
    }
}

__device__ __forceinline__ void gm_stB(uint32_t* __restrict__ Bs, const uint4* p, int tid) {
#pragma unroll
    for (int it = 0; it < 2; it++) {
        int q = tid + it * 256;
        int row = q >> 2, c = q & 3;
        int ks = c >> 1;
        int kk = (c & 1) << 3;
        int reg = kk >> 3;               // b0 (k<8) or b1 (k>=8)
        int Nb = row >> 3, gn = row & 7;
        int base = (Nb * 2 + ks) * 32 + gn * 4;
        const uint32_t* w = (const uint32_t*)&p[it];
        Bs[(base + 0) * 2 + reg] = w[0];
        Bs[(base + 1) * 2 + reg] = w[1];
        Bs[(base + 2) * 2 + reg] = w[2];
        Bs[(base + 3) * 2 + reg] = w[3];
    }
}

__global__ __launch_bounds__(256, 2) void gemm_mma(const __half* __restrict__ A,
                                                   const __half* __restrict__ B,
                                                   const float* __restrict__ bias,
                                                   float* __restrict__ C,
                                                   int M, int N, int K) {
    extern __shared__ uint32_t sm[];
    uint32_t* As = sm;              // [2][GM_BUF]
    uint32_t* Bs = sm + 2 * GM_BUF;

    int tid = threadIdx.x;
    int lane = tid & 31, wid = tid >> 5;
    int warp_m = wid >> 2, warp_n = wid & 3;
    int g = lane >> 2, t = lane & 3;

    int bm = blockIdx.x * GM_BM;
    int bn = blockIdx.y * GM_BN;

    const __half* Aptr = A + (size_t)bm * K;
    const __half* Bptr = B + (size_t)bn * K;

    float acc[4][4][4];
#pragma unroll
    for (int mi = 0; mi < 4; mi++)
#pragma unroll
        for (int ni = 0; ni < 4; ni++)
#pragma unroll
            for (int e = 0; e < 4; e++) acc[mi][ni][e] = 0.0f;

    const int NCH = K / GM_BK;
    int abase = warp_m * 4;    // R offset
    int bbase = warp_n * 4;    // Nb offset

    uint4 sa[2], sb[2];        // staging (A and B)
    gm_ldg(Aptr, K, 0, tid, sa);
    gm_stA(As, sa, tid);
    gm_ldg(Bptr, K, 0, tid, sb);
    gm_stB(Bs, sb, tid);
    __syncthreads();

    for (int i = 0; i < NCH; i++) {
        int buf = i & 1;
        uint32_t* An = As + (buf ^ 1) * GM_BUF;
        uint32_t* Bn = Bs + (buf ^ 1) * GM_BUF;
        const uint32_t* Ab = As + buf * GM_BUF;
        const uint32_t* Bb = Bs + buf * GM_BUF;
        bool stage = (i + 1 < NCH);
        int k1 = (i + 1) * GM_BK;

#pragma unroll
        for (int ks = 0; ks < 2; ks++) {
            uint4 af[4];
            uint2 bf[4];
#pragma unroll
            for (int mi = 0; mi < 4; mi++)
                af[mi] = *(const uint4*)&Ab[(((abase + mi) * 2 + ks) * 32 + lane) * 4];
#pragma unroll
            for (int ni = 0; ni < 4; ni++)
                bf[ni] = *(const uint2*)&Bb[(((bbase + ni) * 2 + ks) * 32 + lane) * 2];
#pragma unroll
            for (int mi = 0; mi < 4; mi++)
#pragma unroll
                for (int ni = 0; ni < 4; ni++)
                    mma_f16(acc[mi][ni], af[mi], bf[ni]);

            // staged copy of next chunk spread across the two ks steps
            if (ks == 0 && stage) { gm_ldg(Aptr, K, k1, tid, sa);
                                    gm_ldg(Bptr, K, k1, tid, sb);
                                    gm_stA(An, sa, tid); }
            if (ks == 1 && stage)   gm_stB(Bn, sb, tid);
        }
        __syncthreads();
    }

    // epilogue: add bias, store (float2 per fragment row)
    int m_base = bm + warp_m * 64;
    int n_base = bn + warp_n * 32;
#pragma unroll
    for (int mi = 0; mi < 4; mi++) {
#pragma unroll
        for (int ni = 0; ni < 4; ni++) {
            int r0 = m_base + mi * 16 + g;
            int col = n_base + ni * 8 + t * 2;
            float b0 = __ldg(&bias[col]);
            float b1 = __ldg(&bias[col + 1]);
            float2 o0 = make_float2(acc[mi][ni][0] + b0, acc[mi][ni][1] + b1);
            float2 o1 = make_float2(acc[mi][ni][2] + b0, acc[mi][ni][3] + b1);
            *(float2*)&C[(size_t)r0 * N + col] = o0;
            *(float2*)&C[(size_t)(r0 + 8) * N + col] = o1;
        }
    }
}

// ---------------- causal attention (flash-style, online softmax) --------------
#define AT_TQ 16
#define AT_TS 64

__global__ __launch_bounds__(256) void attn_kernel(const float* __restrict__ q,
                                                   const float* __restrict__ k,
                                                   const float* __restrict__ v,
                                                   __half* __restrict__ oh) {
    int qt0 = blockIdx.x * AT_TQ;
    int h = blockIdx.y;
    int b = blockIdx.z;

    __shared__ float Qs[AT_TQ][DD + 1];
    __shared__ float Ks[AT_TS][DD + 1];
    __shared__ float Vs[AT_TS][DD + 1];
    __shared__ float Ps[AT_TQ][AT_TS + 1];
    __shared__ float m_s[AT_TQ], l_s[AT_TQ], alpha_s[AT_TQ];

    int tid = threadIdx.x;

    for (int i = tid; i < AT_TQ * DD; i += 256) {
        int r = i >> 6, d = i & 63;
        Qs[r][d] = q[(size_t)(b * TT + qt0 + r) * EE + h * DD + d];
    }
    if (tid < AT_TQ) { m_s[tid] = -1e30f; l_s[tid] = 0.0f; }
    __syncthreads();

    float o_acc[4] = {0.f, 0.f, 0.f, 0.f};
    int d_own = tid & 63;
    int r_base = (tid >> 6) * 4;

    int n_tiles = (qt0 + AT_TQ - 1) / AT_TS + 1;

    for (int kt = 0; kt < n_tiles; kt++) {
        int s0 = kt * AT_TS;
        for (int i = tid; i < AT_TS * DD; i += 256) {
            int r = i >> 6, d = i & 63;
            size_t gi = (size_t)(b * TT + s0 + r) * EE + h * DD + d;
            Ks[r][d] = k[gi];
            Vs[r][d] = v[gi];
        }
        __syncthreads();

        float sacc[4] = {0.f, 0.f, 0.f, 0.f};
#pragma unroll
        for (int d = 0; d < DD; d++) {
            float kv = Ks[d_own][d];
#pragma unroll
            for (int j = 0; j < 4; j++) sacc[j] = fmaf(Qs[r_base + j][d], kv, sacc[j]);
        }
        int s_glob = s0 + d_own;
#pragma unroll
        for (int j = 0; j < 4; j++) {
            int t_glob = qt0 + r_base + j;
            Ps[r_base + j][d_own] = (s_glob <= t_glob) ? sacc[j] : -1e30f;
        }
        __syncthreads();

        int warp = tid >> 5, lane = tid & 31;
#pragma unroll
        for (int rw = 0; rw < 2; rw++) {
            int rr = warp * 2 + rw;
            float x0 = Ps[rr][lane], x1 = Ps[rr][lane + 32];
            float mx = fmaxf(x0, x1);
#pragma unroll
            for (int off = 16; off; off >>= 1)
                mx = fmaxf(mx, __shfl_xor_sync(0xffffffffu, mx, off));
            float m_old = m_s[rr];
            float m_new = fmaxf(m_old, mx);
            float e0 = __expf(x0 - m_new);
            float e1 = __expf(x1 - m_new);
            float sum = e0 + e1;
#pragma unroll
            for (int off = 16; off; off >>= 1)
                sum += __shfl_xor_sync(0xffffffffu, sum, off);
            Ps[rr][lane] = e0;
            Ps[rr][lane + 32] = e1;
            if (lane == 0) {
                float alpha = __expf(m_old - m_new);
                alpha_s[rr] = alpha;
                l_s[rr] = l_s[rr] * alpha + sum;
                m_s[rr] = m_new;
            }
        }
        __syncthreads();

#pragma unroll
        for (int j = 0; j < 4; j++) o_acc[j] *= alpha_s[r_base + j];
#pragma unroll
        for (int s = 0; s < AT_TS; s++) {
            float vv = Vs[s][d_own];
#pragma unroll
            for (int j = 0; j < 4; j++) o_acc[j] = fmaf(Ps[r_base + j][s], vv, o_acc[j]);
        }
        __syncthreads();
    }

#pragma unroll
    for (int j = 0; j < 4; j++) {
        int r = r_base + j;
        oh[(size_t)(b * TT + qt0 + r) * EE + h * DD + d_own] =
            __float2half(o_acc[j] / l_s[r] * 0.125f);
    }
}

// ---------------- per-row logsumexp + per-row loss term -----------------------
__global__ __launch_bounds__(256) void lse_loss_kernel(const float* __restrict__ logits,
                                                       const int* __restrict__ targets,
                                                       float* __restrict__ lterms) {
    int row = blockIdx.x;
    const float* p = logits + (size_t)row * VV;
    float m = -1e30f, l = 0.0f;
    for (int i = threadIdx.x; i < VV; i += 256) {
        float x = p[i];
        if (x > m) { l = l * __expf(m - x) + 1.0f; m = x; }
        else       { l += __expf(x - m); }
    }
    __shared__ float ms[256], ls[256];
    ms[threadIdx.x] = m;
    ls[threadIdx.x] = l;
    __syncthreads();
    for (int s = 128; s; s >>= 1) {
        if (threadIdx.x < (unsigned)s) {
            float m2 = ms[threadIdx.x + s], l2 = ls[threadIdx.x + s];
            float M = fmaxf(ms[threadIdx.x], m2);
            ls[threadIdx.x] = ls[threadIdx.x] * __expf(ms[threadIdx.x] - M) + l2 * __expf(m2 - M);
            ms[threadIdx.x] = M;
        }
        __syncthreads();
    }
    if (threadIdx.x == 0) {
        float lse = ms[0] + logf(ls[0]);
        lterms[row] = lse - p[targets[row]];
    }
}

__global__ __launch_bounds__(256) void loss_reduce(const float* __restrict__ lterms,
                                                   float* __restrict__ out, int do_write) {
    __shared__ float s[256];
    float acc = 0.0f;
    for (int i = threadIdx.x; i < BT; i += 256) acc += lterms[i];
    s[threadIdx.x] = acc;
    __syncthreads();
    for (int st = 128; st; st >>= 1) {
        if (threadIdx.x < (unsigned)st) s[threadIdx.x] += s[threadIdx.x + st];
        __syncthreads();
    }
    if (threadIdx.x == 0 && do_write) out[0] = s[0] / (float)BT;
}

// ------------------------------- launch ---------------------------------------
#define GSM_BYTES (4 * GM_BUF * sizeof(uint32_t))   // 32KB dynamic smem

extern "C" void kernel_launch(void* const* d_in, const int* in_sizes, int n_in,
                              void* d_out, int out_size) {
    const int*   tokens    = (const int*)d_in[0];
    const int*   targets   = (const int*)d_in[1];
    const float* tok_table = (const float*)d_in[2];
    const float* pos_emb   = (const float*)d_in[3];
    const float* Wq        = (const float*)d_in[4];
    const float* bq        = (const float*)d_in[5];
    const float* Wk        = (const float*)d_in[6];
    const float* bk        = (const float*)d_in[7];
    const float* Wv        = (const float*)d_in[8];
    const float* bv        = (const float*)d_in[9];
    const float* Wo        = (const float*)d_in[10];
    const float* bo        = (const float*)d_in[11];
    float* out = (float*)d_out;

    __half *xh, *oh, *wqh, *wkh, *wvh, *woh;
    float *q, *k, *v, *lt;
    cudaGetSymbolAddress((void**)&xh,  g_xh);
    cudaGetSymbolAddress((void**)&oh,  g_oh);
    cudaGetSymbolAddress((void**)&wqh, g_wqh);
    cudaGetSymbolAddress((void**)&wkh, g_wkh);
    cudaGetSymbolAddress((void**)&wvh, g_wvh);
    cudaGetSymbolAddress((void**)&woh, g_woh);
    cudaGetSymbolAddress((void**)&q,   g_q);
    cudaGetSymbolAddress((void**)&k,   g_k);
    cudaGetSymbolAddress((void**)&v,   g_v);
    cudaGetSymbolAddress((void**)&lt,  g_lterms);

    static int smem_set = 0;
    if (!smem_set) {
        cudaFuncSetAttribute(gemm_mma, cudaFuncAttributeMaxDynamicSharedMemorySize,
                             (int)GSM_BYTES);
        smem_set = 1;
    }

    // 1) embedding (fp16) + one-shot weight converts
    embed_kernel<<<(BT * EE / 4) / 256, 256>>>(tokens, tok_table, pos_emb, xh);
    cvt_f2h<<<(EE * EE / 4) / 256, 256>>>(Wq, wqh);
    cvt_f2h<<<(EE * EE / 4) / 256, 256>>>(Wk, wkh);
    cvt_f2h<<<(EE * EE / 4) / 256, 256>>>(Wv, wvh);
    cvt_f2h<<<(VV * EE / 4) / 256, 256>>>(Wo, woh);

    // 2) QKV projections (fp16 mma.sync NT gemms, N=E)
    dim3 gqkv(BT / GM_BM, EE / GM_BN);   // m fastest
    gemm_mma<<<gqkv, 256, GSM_BYTES>>>(xh, wqh, bq, q, BT, EE, EE);
    gemm_mma<<<gqkv, 256, GSM_BYTES>>>(xh, wkh, bk, k, BT, EE, EE);
    gemm_mma<<<gqkv, 256, GSM_BYTES>>>(xh, wvh, bv, v, BT, EE, EE);

    // 3) causal attention -> fp16 O
    attn_kernel<<<dim3(TT / AT_TQ, HH, BB), 256>>>(q, k, v, oh);

    // 4) output projection -> logits into d_out
    dim3 glog(BT / GM_BM, VV / GM_BN);   // m fastest: Wo tile stays L2-resident
    gemm_mma<<<glog, 256, GSM_BYTES>>>(oh, woh, bo, out, BT, VV, EE);

    // 5) loss
    lse_loss_kernel<<<BT, 256>>>(out, targets, lt);
    int write_loss = (out_size > BT * VV) ? 1 : 0;
    loss_reduce<<<1, 256>>>(lt, out + (size_t)BT * VV, write_loss);
}

// round 14
// speedup vs baseline: 1.1199x; 1.0252x over previous
#include <cuda_runtime.h>
#include <cuda_fp16.h>
#include <cstdint>
#include <math.h>

// Problem constants
#define BB 2
#define TT 2048
#define EE 1024
#define HH 16
#define DD 64
#define VV 32000
#define BT (BB * TT)   // 4096

// ---------------- scratch (device globals; no allocations allowed) ------------
__device__ __half g_xh[BT * EE];
__device__ __half g_oh[BT * EE];
__device__ __half g_wqh[EE * EE];
__device__ __half g_wkh[EE * EE];
__device__ __half g_wvh[EE * EE];
__device__ __half g_woh[(size_t)VV * EE];
__device__ float g_q[BT * EE];
__device__ float g_k[BT * EE];
__device__ float g_v[BT * EE];
__device__ float g_lterms[BT];

// ---------------- helpers -----------------------------------------------------
// fp16 m16n8k16, fp32 accumulate
__device__ __forceinline__ void mma_f16(float* d, const uint4& a, const uint2& b) {
    asm volatile(
        "mma.sync.aligned.m16n8k16.row.col.f32.f16.f16.f32 "
        "{%0,%1,%2,%3}, {%4,%5,%6,%7}, {%8,%9}, {%0,%1,%2,%3};"
        : "+f"(d[0]), "+f"(d[1]), "+f"(d[2]), "+f"(d[3])
        : "r"(a.x), "r"(a.y), "r"(a.z), "r"(a.w), "r"(b.x), "r"(b.y));
}

// ---------------- embedding: xh = half(tok_table[tokens] + pos_emb) -----------
__global__ void embed_kernel(const int* __restrict__ tokens,
                             const float* __restrict__ tok_table,
                             const float* __restrict__ pos_emb,
                             __half* __restrict__ xh) {
    int i4 = blockIdx.x * blockDim.x + threadIdx.x;   // over BT*EE/4
    int bt = i4 >> 8;                                  // /(EE/4)
    int e4 = i4 & 255;
    int t = bt & (TT - 1);
    int tok = tokens[bt];
    float4 a = *(const float4*)(tok_table + (size_t)tok * EE + e4 * 4);
    float4 p = *(const float4*)(pos_emb + (size_t)t * EE + e4 * 4);
    __half2 h0 = __floats2half2_rn(a.x + p.x, a.y + p.y);
    __half2 h1 = __floats2half2_rn(a.z + p.z, a.w + p.w);
    *(__half2*)(xh + (size_t)i4 * 4) = h0;
    *(__half2*)(xh + (size_t)i4 * 4 + 2) = h1;
}

// ---------------- fp32 -> fp16 convert (weights, per-launch) ------------------
__global__ void cvt_f2h(const float* __restrict__ src, __half* __restrict__ dst) {
    size_t i = (size_t)blockIdx.x * blockDim.x + threadIdx.x;    // over n/8
    float4 v0 = ((const float4*)src)[i * 2];
    float4 v1 = ((const float4*)src)[i * 2 + 1];
    __half2 h0 = __floats2half2_rn(v0.x, v0.y);
    __half2 h1 = __floats2half2_rn(v0.z, v0.w);
    __half2 h2 = __floats2half2_rn(v1.x, v1.y);
    __half2 h3 = __floats2half2_rn(v1.z, v1.w);
    uint4 packed;
    packed.x = *(uint32_t*)&h0; packed.y = *(uint32_t*)&h1;
    packed.z = *(uint32_t*)&h2; packed.w = *(uint32_t*)&h3;
    ((uint4*)dst)[i] = packed;
}

// ====== mma.sync fp16 NT GEMM (fp16 gmem operands, deferred-STS pipeline) =====
// CTA tile 128x128, BK=32 (2 k-steps of 16). 256 threads, 8 warps (2x4),
// warp tile 64x32 = 4x4 m16n8k16 fragments. fp32 accumulate. 2 CTAs/SM.
// Staging schedule (R9-style deferred STS): ks0 = LDG A + LDG B of chunk i+1;
// ks1 = STS A + STS B. Each LDG gets a full k-step of MMA/LDS cover.
//
// SMEM (fragment-native uint32 arrays, conflict-free):
//   As: [R=8 (16-row blk)][ks=2][lane=32][4]   (2048 u32 = 8KB per buffer)
//   Bs: [Nb=16 (8-col blk)][ks=2][lane=32][2]  (2048 u32 = 8KB per buffer)

#define GM_BM 128
#define GM_BN 128
#define GM_BK 32
#define GM_BUF 2048     // uint32 per As or Bs buffer

__device__ __forceinline__ void gm_ldg(const __half* __restrict__ P, int K, int k0,
                                       int tid, uint4* p) {
#pragma unroll
    for (int it = 0; it < 2; it++) {
        int q = tid + it * 256;          // 0..511
        int row = q >> 2, c = q & 3;     // 4 x 16B chunks per 64B row
        p[it] = *(const uint4*)(P + (size_t)row * K + k0 + c * 8);
    }
}

__device__ __forceinline__ void gm_stA(uint32_t* __restrict__ As, const uint4* p, int tid) {
#pragma unroll
    for (int it = 0; it < 2; it++) {
        int q = tid + it * 256;
        int row = q >> 2, c = q & 3;
        int ks = c >> 1;                 // k16 step
        int kk = (c & 1) << 3;           // 0 or 8 within k16
        int R = row >> 4, r16 = row & 15;
        int g = r16 & 7, hi = r16 >> 3;
        int reg = (kk >> 3) * 2 + hi;    // 0/1 (k<8) or 2/3 (k>=8)
        int base = (R * 2 + ks) * 32 + g * 4;
        const uint32_t* w = (const uint32_t*)&p[it];
        As[(base + 0) * 4 + reg] = w[0];
        As[(base + 1) * 4 + reg] = w[1];
        As[(base + 2) * 4 + reg] = w[2];
        As[(base + 3) * 4 + reg] = w[3];
    }
}

__device__ __forceinline__ void gm_stB(uint32_t* __restrict__ Bs, const uint4* p, int tid) {
#pragma unroll
    for (int it = 0; it < 2; it++) {
        int q = tid + it * 256;
        int row = q >> 2, c = q & 3;
        int ks = c >> 1;
        int kk = (c & 1) << 3;
        int reg = kk >> 3;               // b0 (k<8) or b1 (k>=8)
        int Nb = row >> 3, gn = row & 7;
        int base = (Nb * 2 + ks) * 32 + gn * 4;
        const uint32_t* w = (const uint32_t*)&p[it];
        Bs[(base + 0) * 2 + reg] = w[0];
        Bs[(base + 1) * 2 + reg] = w[1];
        Bs[(base + 2) * 2 + reg] = w[2];
        Bs[(base + 3) * 2 + reg] = w[3];
    }
}

__global__ __launch_bounds__(256, 2) void gemm_mma(const __half* __restrict__ A,
                                                   const __half* __restrict__ B,
                                                   const float* __restrict__ bias,
                                                   float* __restrict__ C,
                                                   int M, int N, int K) {
    extern __shared__ uint32_t sm[];
    uint32_t* As = sm;              // [2][GM_BUF]
    uint32_t* Bs = sm + 2 * GM_BUF;

    int tid = threadIdx.x;
    int lane = tid & 31, wid = tid >> 5;
    int warp_m = wid >> 2, warp_n = wid & 3;
    int g = lane >> 2, t = lane & 3;

    int bm = blockIdx.x * GM_BM;
    int bn = blockIdx.y * GM_BN;

    const __half* Aptr = A + (size_t)bm * K;
    const __half* Bptr = B + (size_t)bn * K;

    float acc[4][4][4];
#pragma unroll
    for (int mi = 0; mi < 4; mi++)
#pragma unroll
        for (int ni = 0; ni < 4; ni++)
#pragma unroll
            for (int e = 0; e < 4; e++) acc[mi][ni][e] = 0.0f;

    const int NCH = K / GM_BK;
    int abase = warp_m * 4;    // R offset
    int bbase = warp_n * 4;    // Nb offset

    uint4 sa[2], sb[2];        // staging (A and B)
    gm_ldg(Aptr, K, 0, tid, sa);
    gm_stA(As, sa, tid);
    gm_ldg(Bptr, K, 0, tid, sb);
    gm_stB(Bs, sb, tid);
    __syncthreads();

    for (int i = 0; i < NCH; i++) {
        int buf = i & 1;
        uint32_t* An = As + (buf ^ 1) * GM_BUF;
        uint32_t* Bn = Bs + (buf ^ 1) * GM_BUF;
        const uint32_t* Ab = As + buf * GM_BUF;
        const uint32_t* Bb = Bs + buf * GM_BUF;
        bool stage = (i + 1 < NCH);
        int k1 = (i + 1) * GM_BK;

#pragma unroll
        for (int ks = 0; ks < 2; ks++) {
            uint4 af[4];
            uint2 bf[4];
#pragma unroll
            for (int mi = 0; mi < 4; mi++)
                af[mi] = *(const uint4*)&Ab[(((abase + mi) * 2 + ks) * 32 + lane) * 4];
#pragma unroll
            for (int ni = 0; ni < 4; ni++)
                bf[ni] = *(const uint2*)&Bb[(((bbase + ni) * 2 + ks) * 32 + lane) * 2];
#pragma unroll
            for (int mi = 0; mi < 4; mi++)
#pragma unroll
                for (int ni = 0; ni < 4; ni++)
                    mma_f16(acc[mi][ni], af[mi], bf[ni]);

            // deferred staging: LDGs a full k-step before their STS
            if (ks == 0 && stage) { gm_ldg(Aptr, K, k1, tid, sa);
                                    gm_ldg(Bptr, K, k1, tid, sb); }
            if (ks == 1 && stage) { gm_stA(An, sa, tid);
                                    gm_stB(Bn, sb, tid); }
        }
        __syncthreads();
    }

    // epilogue: add bias, store (float2 per fragment row)
    int m_base = bm + warp_m * 64;
    int n_base = bn + warp_n * 32;
#pragma unroll
    for (int mi = 0; mi < 4; mi++) {
#pragma unroll
        for (int ni = 0; ni < 4; ni++) {
            int r0 = m_base + mi * 16 + g;
            int col = n_base + ni * 8 + t * 2;
            float b0 = __ldg(&bias[col]);
            float b1 = __ldg(&bias[col + 1]);
            float2 o0 = make_float2(acc[mi][ni][0] + b0, acc[mi][ni][1] + b1);
            float2 o1 = make_float2(acc[mi][ni][2] + b0, acc[mi][ni][3] + b1);
            *(float2*)&C[(size_t)r0 * N + col] = o0;
            *(float2*)&C[(size_t)(r0 + 8) * N + col] = o1;
        }
    }
}

// ---------------- causal attention (flash-style, online softmax) --------------
#define AT_TQ 16
#define AT_TS 64

__global__ __launch_bounds__(256) void attn_kernel(const float* __restrict__ q,
                                                   const float* __restrict__ k,
                                                   const float* __restrict__ v,
                                                   __half* __restrict__ oh) {
    int qt0 = blockIdx.x * AT_TQ;
    int h = blockIdx.y;
    int b = blockIdx.z;

    __shared__ float Qs[AT_TQ][DD + 1];
    __shared__ float Ks[AT_TS][DD + 1];
    __shared__ float Vs[AT_TS][DD + 1];
    __shared__ float Ps[AT_TQ][AT_TS + 1];
    __shared__ float m_s[AT_TQ], l_s[AT_TQ], alpha_s[AT_TQ];

    int tid = threadIdx.x;

    for (int i = tid; i < AT_TQ * DD; i += 256) {
        int r = i >> 6, d = i & 63;
        Qs[r][d] = q[(size_t)(b * TT + qt0 + r) * EE + h * DD + d];
    }
    if (tid < AT_TQ) { m_s[tid] = -1e30f; l_s[tid] = 0.0f; }
    __syncthreads();

    float o_acc[4] = {0.f, 0.f, 0.f, 0.f};
    int d_own = tid & 63;
    int r_base = (tid >> 6) * 4;

    int n_tiles = (qt0 + AT_TQ - 1) / AT_TS + 1;

    for (int kt = 0; kt < n_tiles; kt++) {
        int s0 = kt * AT_TS;
        for (int i = tid; i < AT_TS * DD; i += 256) {
            int r = i >> 6, d = i & 63;
            size_t gi = (size_t)(b * TT + s0 + r) * EE + h * DD + d;
            Ks[r][d] = k[gi];
            Vs[r][d] = v[gi];
        }
        __syncthreads();

        float sacc[4] = {0.f, 0.f, 0.f, 0.f};
#pragma unroll
        for (int d = 0; d < DD; d++) {
            float kv = Ks[d_own][d];
#pragma unroll
            for (int j = 0; j < 4; j++) sacc[j] = fmaf(Qs[r_base + j][d], kv, sacc[j]);
        }
        int s_glob = s0 + d_own;
#pragma unroll
        for (int j = 0; j < 4; j++) {
            int t_glob = qt0 + r_base + j;
            Ps[r_base + j][d_own] = (s_glob <= t_glob) ? sacc[j] : -1e30f;
        }
        __syncthreads();

        int warp = tid >> 5, lane = tid & 31;
#pragma unroll
        for (int rw = 0; rw < 2; rw++) {
            int rr = warp * 2 + rw;
            float x0 = Ps[rr][lane], x1 = Ps[rr][lane + 32];
            float mx = fmaxf(x0, x1);
#pragma unroll
            for (int off = 16; off; off >>= 1)
                mx = fmaxf(mx, __shfl_xor_sync(0xffffffffu, mx, off));
            float m_old = m_s[rr];
            float m_new = fmaxf(m_old, mx);
            float e0 = __expf(x0 - m_new);
            float e1 = __expf(x1 - m_new);
            float sum = e0 + e1;
#pragma unroll
            for (int off = 16; off; off >>= 1)
                sum += __shfl_xor_sync(0xffffffffu, sum, off);
            Ps[rr][lane] = e0;
            Ps[rr][lane + 32] = e1;
            if (lane == 0) {
                float alpha = __expf(m_old - m_new);
                alpha_s[rr] = alpha;
                l_s[rr] = l_s[rr] * alpha + sum;
                m_s[rr] = m_new;
            }
        }
        __syncthreads();

#pragma unroll
        for (int j = 0; j < 4; j++) o_acc[j] *= alpha_s[r_base + j];
#pragma unroll
        for (int s = 0; s < AT_TS; s++) {
            float vv = Vs[s][d_own];
#pragma unroll
            for (int j = 0; j < 4; j++) o_acc[j] = fmaf(Ps[r_base + j][s], vv, o_acc[j]);
        }
        __syncthreads();
    }

#pragma unroll
    for (int j = 0; j < 4; j++) {
        int r = r_base + j;
        oh[(size_t)(b * TT + qt0 + r) * EE + h * DD + d_own] =
            __float2half(o_acc[j] / l_s[r] * 0.125f);
    }
}

// ---------------- per-row logsumexp + per-row loss term -----------------------
__global__ __launch_bounds__(256) void lse_loss_kernel(const float* __restrict__ logits,
                                                       const int* __restrict__ targets,
                                                       float* __restrict__ lterms) {
    int row = blockIdx.x;
    const float* p = logits + (size_t)row * VV;
    float m = -1e30f, l = 0.0f;
    for (int i = threadIdx.x; i < VV; i += 256) {
        float x = p[i];
        if (x > m) { l = l * __expf(m - x) + 1.0f; m = x; }
        else       { l += __expf(x - m); }
    }
    __shared__ float ms[256], ls[256];
    ms[threadIdx.x] = m;
    ls[threadIdx.x] = l;
    __syncthreads();
    for (int s = 128; s; s >>= 1) {
        if (threadIdx.x < (unsigned)s) {
            float m2 = ms[threadIdx.x + s], l2 = ls[threadIdx.x + s];
            float M = fmaxf(ms[threadIdx.x], m2);
            ls[threadIdx.x] = ls[threadIdx.x] * __expf(ms[threadIdx.x] - M) + l2 * __expf(m2 - M);
            ms[threadIdx.x] = M;
        }
        __syncthreads();
    }
    if (threadIdx.x == 0) {
        float lse = ms[0] + logf(ls[0]);
        lterms[row] = lse - p[targets[row]];
    }
}

__global__ __launch_bounds__(256) void loss_reduce(const float* __restrict__ lterms,
                                                   float* __restrict__ out, int do_write) {
    __shared__ float s[256];
    float acc = 0.0f;
    for (int i = threadIdx.x; i < BT; i += 256) acc += lterms[i];
    s[threadIdx.x] = acc;
    __syncthreads();
    for (int st = 128; st; st >>= 1) {
        if (threadIdx.x < (unsigned)st) s[threadIdx.x] += s[threadIdx.x + st];
        __syncthreads();
    }
    if (threadIdx.x == 0 && do_write) out[0] = s[0] / (float)BT;
}

// ------------------------------- launch ---------------------------------------
#define GSM_BYTES (4 * GM_BUF * sizeof(uint32_t))   // 32KB dynamic smem

extern "C" void kernel_launch(void* const* d_in, const int* in_sizes, int n_in,
                              void* d_out, int out_size) {
    const int*   tokens    = (const int*)d_in[0];
    const int*   targets   = (const int*)d_in[1];
    const float* tok_table = (const float*)d_in[2];
    const float* pos_emb   = (const float*)d_in[3];
    const float* Wq        = (const float*)d_in[4];
    const float* bq        = (const float*)d_in[5];
    const float* Wk        = (const float*)d_in[6];
    const float* bk        = (const float*)d_in[7];
    const float* Wv        = (const float*)d_in[8];
    const float* bv        = (const float*)d_in[9];
    const float* Wo        = (const float*)d_in[10];
    const float* bo        = (const float*)d_in[11];
    float* out = (float*)d_out;

    __half *xh, *oh, *wqh, *wkh, *wvh, *woh;
    float *q, *k, *v, *lt;
    cudaGetSymbolAddress((void**)&xh,  g_xh);
    cudaGetSymbolAddress((void**)&oh,  g_oh);
    cudaGetSymbolAddress((void**)&wqh, g_wqh);
    cudaGetSymbolAddress((void**)&wkh, g_wkh);
    cudaGetSymbolAddress((void**)&wvh, g_wvh);
    cudaGetSymbolAddress((void**)&woh, g_woh);
    cudaGetSymbolAddress((void**)&q,   g_q);
    cudaGetSymbolAddress((void**)&k,   g_k);
    cudaGetSymbolAddress((void**)&v,   g_v);
    cudaGetSymbolAddress((void**)&lt,  g_lterms);

    static int smem_set = 0;
    if (!smem_set) {
        cudaFuncSetAttribute(gemm_mma, cudaFuncAttributeMaxDynamicSharedMemorySize,
                             (int)GSM_BYTES);
        smem_set = 1;
    }

    // 1) embedding (fp16) + weight converts (per launch; deterministic)
    embed_kernel<<<(BT * EE / 4) / 256, 256>>>(tokens, tok_table, pos_emb, xh);
    cvt_f2h<<<(EE * EE / 8) / 256, 256>>>(Wq, wqh);
    cvt_f2h<<<(EE * EE / 8) / 256, 256>>>(Wk, wkh);
    cvt_f2h<<<(EE * EE / 8) / 256, 256>>>(Wv, wvh);
    cvt_f2h<<<(VV * EE / 8) / 256, 256>>>(Wo, woh);

    // 2) QKV projections (fp16 mma.sync NT gemms, N=E)
    dim3 gqkv(BT / GM_BM, EE / GM_BN);   // m fastest
    gemm_mma<<<gqkv, 256, GSM_BYTES>>>(xh, wqh, bq, q, BT, EE, EE);
    gemm_mma<<<gqkv, 256, GSM_BYTES>>>(xh, wkh, bk, k, BT, EE, EE);
    gemm_mma<<<gqkv, 256, GSM_BYTES>>>(xh, wvh, bv, v, BT, EE, EE);

    // 3) causal attention -> fp16 O
    attn_kernel<<<dim3(TT / AT_TQ, HH, BB), 256>>>(q, k, v, oh);

    // 4) output projection -> logits into d_out
    dim3 glog(BT / GM_BM, VV / GM_BN);   // m fastest: Wo tile stays L2-resident
    gemm_mma<<<glog, 256, GSM_BYTES>>>(oh, woh, bo, out, BT, VV, EE);

    // 5) loss
    lse_loss_kernel<<<BT, 256>>>(out, targets, lt);
    int write_loss = (out_size > BT * VV) ? 1 : 0;
    loss_reduce<<<1, 256>>>(lt, out + (size_t)BT * VV, write_loss);
}

// round 15
// speedup vs baseline: 1.2360x; 1.1036x over previous
#include <cuda_runtime.h>
#include <cuda_fp16.h>
#include <cstdint>
#include <math.h>

// Problem constants
#define BB 2
#define TT 2048
#define EE 1024
#define HH 16
#define DD 64
#define VV 32000
#define BT (BB * TT)   // 4096
#define NBL 250        // logits n-blocks (VV/128)

// ---------------- scratch (device globals; no allocations allowed) ------------
__device__ float g_x[BT * EE];
__device__ float g_q[BT * EE];
__device__ float g_k[BT * EE];
__device__ float g_v[BT * EE];
__device__ float g_o[BT * EE];
__device__ float g_lterms[BT];
__device__ float2 g_lsep[(size_t)BT * NBL];   // per-(row, n-block) partial (max, sumexp)

// ---------------- helpers -----------------------------------------------------
__device__ __forceinline__ uint32_t pack_h2(float lo, float hi) {
    __half2 h = __floats2half2_rn(lo, hi);   // lo -> .x (low 16 bits)
    return *(uint32_t*)&h;
}

// fp16 m16n8k16, fp32 accumulate
__device__ __forceinline__ void mma_f16(float* d, const uint4& a, const uint2& b) {
    asm volatile(
        "mma.sync.aligned.m16n8k16.row.col.f32.f16.f16.f32 "
        "{%0,%1,%2,%3}, {%4,%5,%6,%7}, {%8,%9}, {%0,%1,%2,%3};"
        : "+f"(d[0]), "+f"(d[1]), "+f"(d[2]), "+f"(d[3])
        : "r"(a.x), "r"(a.y), "r"(a.z), "r"(a.w), "r"(b.x), "r"(b.y));
}

// ---------------- embedding: x = tok_table[tokens] + pos_emb ------------------
__global__ void embed_kernel(const int* __restrict__ tokens,
                             const float* __restrict__ tok_table,
                             const float* __restrict__ pos_emb,
                             float* __restrict__ x) {
    int idx = blockIdx.x * blockDim.x + threadIdx.x;  // over BT*EE
    int bt = idx >> 10;
    int e  = idx & (EE - 1);
    int t  = bt & (TT - 1);
    int tok = tokens[bt];
    x[idx] = tok_table[tok * EE + e] + pos_emb[t * EE + e];
}

// ====== mma.sync fp16 NT GEMM (R9-exact mainloop) + optional fused LSE ========
// CTA tile 128x128, BK=32 (2 k-steps of 16). 256 threads, 8 warps (2x4),
// warp tile 64x32 = 4x4 m16n8k16 fragments. fp32 accumulate. 2 CTAs/SM.
// fp32 gmem operands, converted fp32->fp16 (RN) at the STS stage.

#define GM_BM 128
#define GM_BN 128
#define GM_BK 32
#define GM_BUF 2048     // uint32 per As or Bs buffer

__device__ __forceinline__ void gm_ldg(const float* __restrict__ P, int K, int k0,
                                       int tid, float4* p) {
#pragma unroll
    for (int it = 0; it < 4; it++) {
        int q = tid + it * 256;
        int row = q >> 3, c = q & 7;
        p[it] = *(const float4*)(P + (size_t)row * K + k0 + c * 4);
    }
}

__device__ __forceinline__ void gm_stA(uint32_t* __restrict__ As, const float4* p, int tid) {
#pragma unroll
    for (int it = 0; it < 4; it++) {
        int q = tid + it * 256;
        int row = q >> 3, c = q & 7;
        int ks = c >> 2;                 // 0..1 (k16 step)
        int kk = (c & 3) << 2;           // 0,4,8,12 within k16
        int rh = kk >> 3;                // 0: regs 0/1, 1: regs 2/3
        int tp = (kk & 7) >> 1;          // thread pair base 0 or 2
        int R = row >> 4, r16 = row & 15;
        int g = r16 & 7, hi = r16 >> 3;
        int reg = rh * 2 + hi;
        int base = ((R * 2 + ks) * 32 + g * 4);
        As[(base + tp + 0) * 4 + reg] = pack_h2(p[it].x, p[it].y);
        As[(base + tp + 1) * 4 + reg] = pack_h2(p[it].z, p[it].w);
    }
}

__device__ __forceinline__ void gm_stB(uint32_t* __restrict__ Bs, const float4* p, int tid) {
#pragma unroll
    for (int it = 0; it < 4; it++) {
        int q = tid + it * 256;
        int row = q >> 3, c = q & 7;
        int ks = c >> 2;
        int kk = (c & 3) << 2;
        int reg = kk >> 3;               // b0 (k<8) or b1 (k>=8)
        int tp = (kk & 7) >> 1;
        int Nb = row >> 3, gn = row & 7;
        int base = ((Nb * 2 + ks) * 32 + gn * 4);
        Bs[(base + tp + 0) * 2 + reg] = pack_h2(p[it].x, p[it].y);
        Bs[(base + tp + 1) * 2 + reg] = pack_h2(p[it].z, p[it].w);
    }
}

__global__ __launch_bounds__(256, 2) void gemm_mma(const float* __restrict__ A,
                                                   const float* __restrict__ B,
                                                   const float* __restrict__ bias,
                                                   float* __restrict__ C,
                                                   int M, int N, int K,
                                                   float2* __restrict__ lse_part) {
    extern __shared__ uint32_t sm[];
    uint32_t* As = sm;              // [2][GM_BUF]
    uint32_t* Bs = sm + 2 * GM_BUF;

    int tid = threadIdx.x;
    int lane = tid & 31, wid = tid >> 5;
    int warp_m = wid >> 2, warp_n = wid & 3;
    int g = lane >> 2, t = lane & 3;

    int bm = blockIdx.x * GM_BM;
    int bn = blockIdx.y * GM_BN;

    const float* Aptr = A + (size_t)bm * K;
    const float* Bptr = B + (size_t)bn * K;

    float acc[4][4][4];
#pragma unroll
    for (int mi = 0; mi < 4; mi++)
#pragma unroll
        for (int ni = 0; ni < 4; ni++)
#pragma unroll
            for (int e = 0; e < 4; e++) acc[mi][ni][e] = 0.0f;

    const int NCH = K / GM_BK;
    int abase = warp_m * 4;    // R offset
    int bbase = warp_n * 4;    // Nb offset

    float4 st[4];              // single staging array (A then B)
    gm_ldg(Aptr, K, 0, tid, st);
    gm_stA(As, st, tid);
    gm_ldg(Bptr, K, 0, tid, st);
    gm_stB(Bs, st, tid);
    __syncthreads();

    for (int i = 0; i < NCH; i++) {
        int buf = i & 1;
        uint32_t* An = As + (buf ^ 1) * GM_BUF;
        uint32_t* Bn = Bs + (buf ^ 1) * GM_BUF;
        const uint32_t* Ab = As + buf * GM_BUF;
        const uint32_t* Bb = Bs + buf * GM_BUF;
        bool stage = (i + 1 < NCH);
        int k1 = (i + 1) * GM_BK;

#pragma unroll
        for (int ks = 0; ks < 2; ks++) {
            uint4 af[4];
            uint2 bf[4];
#pragma unroll
            for (int mi = 0; mi < 4; mi++)
                af[mi] = *(const uint4*)&Ab[(((abase + mi) * 2 + ks) * 32 + lane) * 4];
#pragma unroll
            for (int ni = 0; ni < 4; ni++)
                bf[ni] = *(const uint2*)&Bb[(((bbase + ni) * 2 + ks) * 32 + lane) * 2];
#pragma unroll
            for (int mi = 0; mi < 4; mi++)
#pragma unroll
                for (int ni = 0; ni < 4; ni++)
                    mma_f16(acc[mi][ni], af[mi], bf[ni]);

            // staged copy of next chunk spread across the two ks steps (R9-exact)
            if (ks == 0 && stage) { gm_ldg(Aptr, K, k1, tid, st);
                                    gm_stA(An, st, tid);
                                    gm_ldg(Bptr, K, k1, tid, st); }
            if (ks == 1 && stage)   gm_stB(Bn, st, tid);
        }
        __syncthreads();
    }

    // epilogue: add bias, store; optional fused LSE partials (fp16x2 exp)
    int m_base = bm + warp_m * 64;
    int n_base = bn + warp_n * 32;
    float2* smem_lse = (float2*)sm;   // reuse smem: [128 rows][4 warp_n]

#pragma unroll
    for (int mi = 0; mi < 4; mi++) {
        float m0 = -1e30f, m1 = -1e30f;
#pragma unroll
        for (int ni = 0; ni < 4; ni++) {
            int r0 = m_base + mi * 16 + g;
            int col = n_base + ni * 8 + t * 2;
            float b0 = __ldg(&bias[col]);
            float b1 = __ldg(&bias[col + 1]);
            float v0 = acc[mi][ni][0] + b0;
            float v1 = acc[mi][ni][1] + b1;
            float v2 = acc[mi][ni][2] + b0;
            float v3 = acc[mi][ni][3] + b1;
            acc[mi][ni][0] = v0; acc[mi][ni][1] = v1;
            acc[mi][ni][2] = v2; acc[mi][ni][3] = v3;
            *(float2*)&C[(size_t)r0 * N + col] = make_float2(v0, v1);
            *(float2*)&C[(size_t)(r0 + 8) * N + col] = make_float2(v2, v3);
            m0 = fmaxf(m0, fmaxf(v0, v1));
            m1 = fmaxf(m1, fmaxf(v2, v3));
        }
        if (lse_part) {
            // max over the 4 t-lanes of this row slice
            m0 = fmaxf(m0, __shfl_xor_sync(0xffffffffu, m0, 1));
            m0 = fmaxf(m0, __shfl_xor_sync(0xffffffffu, m0, 2));
            m1 = fmaxf(m1, __shfl_xor_sync(0xffffffffu, m1, 1));
            m1 = fmaxf(m1, __shfl_xor_sync(0xffffffffu, m1, 2));
            float s0 = 0.0f, s1 = 0.0f;
#pragma unroll
            for (int ni = 0; ni < 4; ni++) {
                __half2 e0 = h2exp(__floats2half2_rn(acc[mi][ni][0] - m0,
                                                     acc[mi][ni][1] - m0));
                __half2 e1 = h2exp(__floats2half2_rn(acc[mi][ni][2] - m1,
                                                     acc[mi][ni][3] - m1));
                float2 f0 = __half22float2(e0);
                float2 f1 = __half22float2(e1);
                s0 += f0.x + f0.y;
                s1 += f1.x + f1.y;
            }
            s0 += __shfl_xor_sync(0xffffffffu, s0, 1);
            s0 += __shfl_xor_sync(0xffffffffu, s0, 2);
            s1 += __shfl_xor_sync(0xffffffffu, s1, 1);
            s1 += __shfl_xor_sync(0xffffffffu, s1, 2);
            if (t == 0) {
                int rl0 = warp_m * 64 + mi * 16 + g;       // local row (hi=0)
                smem_lse[rl0 * 4 + warp_n] = make_float2(m0, s0);
                smem_lse[(rl0 + 8) * 4 + warp_n] = make_float2(m1, s1);
            }
        }
    }

    if (lse_part) {
        __syncthreads();
        if (tid < 128) {
            float2 p = smem_lse[tid * 4 + 0];
            float M = p.x, L = p.y;
#pragma unroll
            for (int w = 1; w < 4; w++) {
                float2 pw = smem_lse[tid * 4 + w];
                float nm = fmaxf(M, pw.x);
                L = L * __expf(M - nm) + pw.y * __expf(pw.x - nm);
                M = nm;
            }
            lse_part[(size_t)(bm + tid) * NBL + blockIdx.y] = make_float2(M, L);
        }
    }
}

// ---------------- causal attention (flash-style, online softmax) --------------
#define AT_TQ 16
#define AT_TS 64

__global__ __launch_bounds__(256) void attn_kernel(const float* __restrict__ q,
                                                   const float* __restrict__ k,
                                                   const float* __restrict__ v,
                                                   float* __restrict__ o) {
    int qt0 = blockIdx.x * AT_TQ;
    int h = blockIdx.y;
    int b = blockIdx.z;

    __shared__ float Qs[AT_TQ][DD + 1];
    __shared__ float Ks[AT_TS][DD + 1];
    __shared__ float Vs[AT_TS][DD + 1];
    __shared__ float Ps[AT_TQ][AT_TS + 1];
    __shared__ float m_s[AT_TQ], l_s[AT_TQ], alpha_s[AT_TQ];

    int tid = threadIdx.x;

    for (int i = tid; i < AT_TQ * DD; i += 256) {
        int r = i >> 6, d = i & 63;
        Qs[r][d] = q[(size_t)(b * TT + qt0 + r) * EE + h * DD + d];
    }
    if (tid < AT_TQ) { m_s[tid] = -1e30f; l_s[tid] = 0.0f; }
    __syncthreads();

    float o_acc[4] = {0.f, 0.f, 0.f, 0.f};
    int d_own = tid & 63;
    int r_base = (tid >> 6) * 4;

    int n_tiles = (qt0 + AT_TQ - 1) / AT_TS + 1;

    for (int kt = 0; kt < n_tiles; kt++) {
        int s0 = kt * AT_TS;
        for (int i = tid; i < AT_TS * DD; i += 256) {
            int r = i >> 6, d = i & 63;
            size_t gi = (size_t)(b * TT + s0 + r) * EE + h * DD + d;
            Ks[r][d] = k[gi];
            Vs[r][d] = v[gi];
        }
        __syncthreads();

        float sacc[4] = {0.f, 0.f, 0.f, 0.f};
#pragma unroll
        for (int d = 0; d < DD; d++) {
            float kv = Ks[d_own][d];
#pragma unroll
            for (int j = 0; j < 4; j++) sacc[j] = fmaf(Qs[r_base + j][d], kv, sacc[j]);
        }
        int s_glob = s0 + d_own;
#pragma unroll
        for (int j = 0; j < 4; j++) {
            int t_glob = qt0 + r_base + j;
            Ps[r_base + j][d_own] = (s_glob <= t_glob) ? sacc[j] : -1e30f;
        }
        __syncthreads();

        int warp = tid >> 5, lane = tid & 31;
#pragma unroll
        for (int rw = 0; rw < 2; rw++) {
            int rr = warp * 2 + rw;
            float x0 = Ps[rr][lane], x1 = Ps[rr][lane + 32];
            float mx = fmaxf(x0, x1);
#pragma unroll
            for (int off = 16; off; off >>= 1)
                mx = fmaxf(mx, __shfl_xor_sync(0xffffffffu, mx, off));
            float m_old = m_s[rr];
            float m_new = fmaxf(m_old, mx);
            float e0 = __expf(x0 - m_new);
            float e1 = __expf(x1 - m_new);
            float sum = e0 + e1;
#pragma unroll
            for (int off = 16; off; off >>= 1)
                sum += __shfl_xor_sync(0xffffffffu, sum, off);
            Ps[rr][lane] = e0;
            Ps[rr][lane + 32] = e1;
            if (lane == 0) {
                float alpha = __expf(m_old - m_new);
                alpha_s[rr] = alpha;
                l_s[rr] = l_s[rr] * alpha + sum;
                m_s[rr] = m_new;
            }
        }
        __syncthreads();

#pragma unroll
        for (int j = 0; j < 4; j++) o_acc[j] *= alpha_s[r_base + j];
#pragma unroll
        for (int s = 0; s < AT_TS; s++) {
            float vv = Vs[s][d_own];
#pragma unroll
            for (int j = 0; j < 4; j++) o_acc[j] = fmaf(Ps[r_base + j][s], vv, o_acc[j]);
        }
        __syncthreads();
    }

#pragma unroll
    for (int j = 0; j < 4; j++) {
        int r = r_base + j;
        o[(size_t)(b * TT + qt0 + r) * EE + h * DD + d_own] =
            o_acc[j] / l_s[r] * 0.125f;
    }
}

// ---------------- combine LSE partials + per-row loss term --------------------
// one warp per row; 4 rows per block
__global__ __launch_bounds__(128) void lse_combine(const float2* __restrict__ part,
                                                   const float* __restrict__ logits,
                                                   const int* __restrict__ targets,
                                                   float* __restrict__ lterms) {
    int r = blockIdx.x * 4 + (threadIdx.x >> 5);
    int lane = threadIdx.x & 31;
    const float2* pr = part + (size_t)r * NBL;

    float M = -1e30f, L = 0.0f;
    for (int j = lane; j < NBL; j += 32) {
        float2 p = pr[j];
        float nm = fmaxf(M, p.x);
        L = L * __expf(M - nm) + p.y * __expf(p.x - nm);
        M = nm;
    }
#pragma unroll
    for (int off = 16; off; off >>= 1) {
        float Mo = __shfl_xor_sync(0xffffffffu, M, off);
        float Lo = __shfl_xor_sync(0xffffffffu, L, off);
        float nm = fmaxf(M, Mo);
        L = L * __expf(M - nm) + Lo * __expf(Mo - nm);
        M = nm;
    }
    if (lane == 0) {
        float lse = M + logf(L);
        lterms[r] = lse - __ldg(&logits[(size_t)r * VV + targets[r]]);
    }
}

__global__ __launch_bounds__(256) void loss_reduce(const float* __restrict__ lterms,
                                                   float* __restrict__ out, int do_write) {
    __shared__ float s[256];
    float acc = 0.0f;
    for (int i = threadIdx.x; i < BT; i += 256) acc += lterms[i];
    s[threadIdx.x] = acc;
    __syncthreads();
    for (int st = 128; st; st >>= 1) {
        if (threadIdx.x < (unsigned)st) s[threadIdx.x] += s[threadIdx.x + st];
        __syncthreads();
    }
    if (threadIdx.x == 0 && do_write) out[0] = s[0] / (float)BT;
}

// ------------------------------- launch ---------------------------------------
#define GSM_BYTES (4 * GM_BUF * sizeof(uint32_t))   // 32KB dynamic smem

extern "C" void kernel_launch(void* const* d_in, const int* in_sizes, int n_in,
                              void* d_out, int out_size) {
    const int*   tokens    = (const int*)d_in[0];
    const int*   targets   = (const int*)d_in[1];
    const float* tok_table = (const float*)d_in[2];
    const float* pos_emb   = (const float*)d_in[3];
    const float* Wq        = (const float*)d_in[4];
    const float* bq        = (const float*)d_in[5];
    const float* Wk        = (const float*)d_in[6];
    const float* bk        = (const float*)d_in[7];
    const float* Wv        = (const float*)d_in[8];
    const float* bv        = (const float*)d_in[9];
    const float* Wo        = (const float*)d_in[10];
    const float* bo        = (const float*)d_in[11];
    float* out = (float*)d_out;

    float *x, *q, *k, *v, *o, *lt;
    float2* lsep;
    cudaGetSymbolAddress((void**)&x,    g_x);
    cudaGetSymbolAddress((void**)&q,    g_q);
    cudaGetSymbolAddress((void**)&k,    g_k);
    cudaGetSymbolAddress((void**)&v,    g_v);
    cudaGetSymbolAddress((void**)&o,    g_o);
    cudaGetSymbolAddress((void**)&lt,   g_lterms);
    cudaGetSymbolAddress((void**)&lsep, g_lsep);

    static int smem_set = 0;
    if (!smem_set) {
        cudaFuncSetAttribute(gemm_mma, cudaFuncAttributeMaxDynamicSharedMemorySize,
                             (int)GSM_BYTES);
        smem_set = 1;
    }

    // 1) embedding
    embed_kernel<<<(BT * EE) / 256, 256>>>(tokens, tok_table, pos_emb, x);

    // 2) QKV projections (fp16 mma.sync NT gemms, N=E)
    dim3 gqkv(BT / GM_BM, EE / GM_BN);   // m fastest
    gemm_mma<<<gqkv, 256, GSM_BYTES>>>(x, Wq, bq, q, BT, EE, EE, nullptr);
    gemm_mma<<<gqkv, 256, GSM_BYTES>>>(x, Wk, bk, k, BT, EE, EE, nullptr);
    gemm_mma<<<gqkv, 256, GSM_BYTES>>>(x, Wv, bv, v, BT, EE, EE, nullptr);

    // 3) causal attention
    attn_kernel<<<dim3(TT / AT_TQ, HH, BB), 256>>>(q, k, v, o);

    // 4) output projection -> logits into d_out, with fused LSE partials
    dim3 glog(BT / GM_BM, VV / GM_BN);   // m fastest: Wo tile stays L2-resident
    gemm_mma<<<glog, 256, GSM_BYTES>>>(o, Wo, bo, out, BT, VV, EE, lsep);

    // 5) loss: combine partials, then reduce
    lse_combine<<<BT / 4, 128>>>(lsep, out, targets, lt);
    int write_loss = (out_size > BT * VV) ? 1 : 0;
    loss_reduce<<<1, 256>>>(lt, out + (size_t)BT * VV, write_loss);
}

// round 16
// speedup vs baseline: 1.9514x; 1.5788x over previous
#include <cuda_runtime.h>
#include <cuda_fp16.h>
#include <cstdint>
#include <math.h>

// Problem constants
#define BB 2
#define TT 2048
#define EE 1024
#define HH 16
#define DD 64
#define VV 32000
#define BT (BB * TT)   // 4096
#define NBL 250        // logits n-blocks (VV/128)

// ---------------- scratch (device globals; no allocations allowed) ------------
__device__ float g_x[BT * EE];
__device__ float g_q[BT * EE];
__device__ float g_k[BT * EE];
__device__ float g_v[BT * EE];
__device__ float g_o[BT * EE];
__device__ float g_lterms[BT];
__device__ float2 g_lsep[(size_t)BT * NBL];   // per-(row, n-block) partial (max, sumexp)

// ---------------- helpers -----------------------------------------------------
__device__ __forceinline__ uint32_t pack_h2(float lo, float hi) {
    __half2 h = __floats2half2_rn(lo, hi);   // lo -> .x (low 16 bits)
    return *(uint32_t*)&h;
}

// fp16 m16n8k16, fp32 accumulate
__device__ __forceinline__ void mma_f16(float* d, const uint4& a, const uint2& b) {
    asm volatile(
        "mma.sync.aligned.m16n8k16.row.col.f32.f16.f16.f32 "
        "{%0,%1,%2,%3}, {%4,%5,%6,%7}, {%8,%9}, {%0,%1,%2,%3};"
        : "+f"(d[0]), "+f"(d[1]), "+f"(d[2]), "+f"(d[3])
        : "r"(a.x), "r"(a.y), "r"(a.z), "r"(a.w), "r"(b.x), "r"(b.y));
}

// ---------------- embedding: x = tok_table[tokens] + pos_emb ------------------
__global__ void embed_kernel(const int* __restrict__ tokens,
                             const float* __restrict__ tok_table,
                             const float* __restrict__ pos_emb,
                             float* __restrict__ x) {
    int idx = blockIdx.x * blockDim.x + threadIdx.x;  // over BT*EE
    int bt = idx >> 10;
    int e  = idx & (EE - 1);
    int t  = bt & (TT - 1);
    int tok = tokens[bt];
    x[idx] = tok_table[tok * EE + e] + pos_emb[t * EE + e];
}

// ====== mma.sync fp16 NT GEMM (R9-exact mainloop) + optional fused LSE ========
#define GM_BM 128
#define GM_BN 128
#define GM_BK 32
#define GM_BUF 2048     // uint32 per As or Bs buffer

__device__ __forceinline__ void gm_ldg(const float* __restrict__ P, int K, int k0,
                                       int tid, float4* p) {
#pragma unroll
    for (int it = 0; it < 4; it++) {
        int q = tid + it * 256;
        int row = q >> 3, c = q & 7;
        p[it] = *(const float4*)(P + (size_t)row * K + k0 + c * 4);
    }
}

__device__ __forceinline__ void gm_stA(uint32_t* __restrict__ As, const float4* p, int tid) {
#pragma unroll
    for (int it = 0; it < 4; it++) {
        int q = tid + it * 256;
        int row = q >> 3, c = q & 7;
        int ks = c >> 2;
        int kk = (c & 3) << 2;
        int rh = kk >> 3;
        int tp = (kk & 7) >> 1;
        int R = row >> 4, r16 = row & 15;
        int g = r16 & 7, hi = r16 >> 3;
        int reg = rh * 2 + hi;
        int base = ((R * 2 + ks) * 32 + g * 4);
        As[(base + tp + 0) * 4 + reg] = pack_h2(p[it].x, p[it].y);
        As[(base + tp + 1) * 4 + reg] = pack_h2(p[it].z, p[it].w);
    }
}

__device__ __forceinline__ void gm_stB(uint32_t* __restrict__ Bs, const float4* p, int tid) {
#pragma unroll
    for (int it = 0; it < 4; it++) {
        int q = tid + it * 256;
        int row = q >> 3, c = q & 7;
        int ks = c >> 2;
        int kk = (c & 3) << 2;
        int reg = kk >> 3;
        int tp = (kk & 7) >> 1;
        int Nb = row >> 3, gn = row & 7;
        int base = ((Nb * 2 + ks) * 32 + gn * 4);
        Bs[(base + tp + 0) * 2 + reg] = pack_h2(p[it].x, p[it].y);
        Bs[(base + tp + 1) * 2 + reg] = pack_h2(p[it].z, p[it].w);
    }
}

__global__ __launch_bounds__(256, 2) void gemm_mma(const float* __restrict__ A,
                                                   const float* __restrict__ B,
                                                   const float* __restrict__ bias,
                                                   float* __restrict__ C,
                                                   int M, int N, int K,
                                                   float2* __restrict__ lse_part) {
    extern __shared__ uint32_t sm[];
    uint32_t* As = sm;              // [2][GM_BUF]
    uint32_t* Bs = sm + 2 * GM_BUF;

    int tid = threadIdx.x;
    int lane = tid & 31, wid = tid >> 5;
    int warp_m = wid >> 2, warp_n = wid & 3;
    int g = lane >> 2, t = lane & 3;

    int bm = blockIdx.x * GM_BM;
    int bn = blockIdx.y * GM_BN;

    const float* Aptr = A + (size_t)bm * K;
    const float* Bptr = B + (size_t)bn * K;

    float acc[4][4][4];
#pragma unroll
    for (int mi = 0; mi < 4; mi++)
#pragma unroll
        for (int ni = 0; ni < 4; ni++)
#pragma unroll
            for (int e = 0; e < 4; e++) acc[mi][ni][e] = 0.0f;

    const int NCH = K / GM_BK;
    int abase = warp_m * 4;
    int bbase = warp_n * 4;

    float4 st[4];
    gm_ldg(Aptr, K, 0, tid, st);
    gm_stA(As, st, tid);
    gm_ldg(Bptr, K, 0, tid, st);
    gm_stB(Bs, st, tid);
    __syncthreads();

    for (int i = 0; i < NCH; i++) {
        int buf = i & 1;
        uint32_t* An = As + (buf ^ 1) * GM_BUF;
        uint32_t* Bn = Bs + (buf ^ 1) * GM_BUF;
        const uint32_t* Ab = As + buf * GM_BUF;
        const uint32_t* Bb = Bs + buf * GM_BUF;
        bool stage = (i + 1 < NCH);
        int k1 = (i + 1) * GM_BK;

#pragma unroll
        for (int ks = 0; ks < 2; ks++) {
            uint4 af[4];
            uint2 bf[4];
#pragma unroll
            for (int mi = 0; mi < 4; mi++)
                af[mi] = *(const uint4*)&Ab[(((abase + mi) * 2 + ks) * 32 + lane) * 4];
#pragma unroll
            for (int ni = 0; ni < 4; ni++)
                bf[ni] = *(const uint2*)&Bb[(((bbase + ni) * 2 + ks) * 32 + lane) * 2];
#pragma unroll
            for (int mi = 0; mi < 4; mi++)
#pragma unroll
                for (int ni = 0; ni < 4; ni++)
                    mma_f16(acc[mi][ni], af[mi], bf[ni]);

            if (ks == 0 && stage) { gm_ldg(Aptr, K, k1, tid, st);
                                    gm_stA(An, st, tid);
                                    gm_ldg(Bptr, K, k1, tid, st); }
            if (ks == 1 && stage)   gm_stB(Bn, st, tid);
        }
        __syncthreads();
    }

    // epilogue: add bias, store; optional fused LSE partials
    int m_base = bm + warp_m * 64;
    int n_base = bn + warp_n * 32;
    float2* smem_lse = (float2*)sm;

#pragma unroll
    for (int mi = 0; mi < 4; mi++) {
        float m0 = -1e30f, m1 = -1e30f;
#pragma unroll
        for (int ni = 0; ni < 4; ni++) {
            int r0 = m_base + mi * 16 + g;
            int col = n_base + ni * 8 + t * 2;
            float b0 = __ldg(&bias[col]);
            float b1 = __ldg(&bias[col + 1]);
            float v0 = acc[mi][ni][0] + b0;
            float v1 = acc[mi][ni][1] + b1;
            float v2 = acc[mi][ni][2] + b0;
            float v3 = acc[mi][ni][3] + b1;
            acc[mi][ni][0] = v0; acc[mi][ni][1] = v1;
            acc[mi][ni][2] = v2; acc[mi][ni][3] = v3;
            *(float2*)&C[(size_t)r0 * N + col] = make_float2(v0, v1);
            *(float2*)&C[(size_t)(r0 + 8) * N + col] = make_float2(v2, v3);
            m0 = fmaxf(m0, fmaxf(v0, v1));
            m1 = fmaxf(m1, fmaxf(v2, v3));
        }
        if (lse_part) {
            m0 = fmaxf(m0, __shfl_xor_sync(0xffffffffu, m0, 1));
            m0 = fmaxf(m0, __shfl_xor_sync(0xffffffffu, m0, 2));
            m1 = fmaxf(m1, __shfl_xor_sync(0xffffffffu, m1, 1));
            m1 = fmaxf(m1, __shfl_xor_sync(0xffffffffu, m1, 2));
            float s0 = 0.0f, s1 = 0.0f;
#pragma unroll
            for (int ni = 0; ni < 4; ni++) {
                __half2 e0 = h2exp(__floats2half2_rn(acc[mi][ni][0] - m0,
                                                     acc[mi][ni][1] - m0));
                __half2 e1 = h2exp(__floats2half2_rn(acc[mi][ni][2] - m1,
                                                     acc[mi][ni][3] - m1));
                float2 f0 = __half22float2(e0);
                float2 f1 = __half22float2(e1);
                s0 += f0.x + f0.y;
                s1 += f1.x + f1.y;
            }
            s0 += __shfl_xor_sync(0xffffffffu, s0, 1);
            s0 += __shfl_xor_sync(0xffffffffu, s0, 2);
            s1 += __shfl_xor_sync(0xffffffffu, s1, 1);
            s1 += __shfl_xor_sync(0xffffffffu, s1, 2);
            if (t == 0) {
                int rl0 = warp_m * 64 + mi * 16 + g;
                smem_lse[rl0 * 4 + warp_n] = make_float2(m0, s0);
                smem_lse[(rl0 + 8) * 4 + warp_n] = make_float2(m1, s1);
            }
        }
    }

    if (lse_part) {
        __syncthreads();
        if (tid < 128) {
            float2 p = smem_lse[tid * 4 + 0];
            float M = p.x, L = p.y;
#pragma unroll
            for (int w = 1; w < 4; w++) {
                float2 pw = smem_lse[tid * 4 + w];
                float nm = fmaxf(M, pw.x);
                L = L * __expf(M - nm) + pw.y * __expf(pw.x - nm);
                M = nm;
            }
            lse_part[(size_t)(bm + tid) * NBL + blockIdx.y] = make_float2(M, L);
        }
    }
}

// ---------------- tensorized causal flash attention ---------------------------
// Block = 64 q rows of one (b,h), 128 threads (4 warps x 16 rows).
// KV tiles of 64. S = Q K^T and O += P V via m16n8k16, fp32 softmax.
// K/V staged in fragment-native smem (same u32 convention as gemm_mma).
__global__ __launch_bounds__(128) void attn_mma(const float* __restrict__ q,
                                                const float* __restrict__ k,
                                                const float* __restrict__ v,
                                                float* __restrict__ o) {
    __shared__ uint32_t Ks[2048];   // [nb8][ks4][lane32][2]
    __shared__ uint32_t Vs[2048];

    int tid = threadIdx.x, lane = tid & 31, wid = tid >> 5;
    int qt0 = blockIdx.x * 64;
    int h = blockIdx.y, b = blockIdx.z;
    int g = lane >> 2, t = lane & 3;

    size_t base = (size_t)(b * TT) * EE + h * DD;

    // Q a-frags (resident): rows qt0 + wid*16 + {g, g+8}
    int qrow0 = qt0 + wid * 16 + g;
    const float* qp0 = q + base + (size_t)qrow0 * EE;
    const float* qp1 = qp0 + (size_t)8 * EE;
    uint4 qa[4];
#pragma unroll
    for (int ks = 0; ks < 4; ks++) {
        float2 f0 = *(const float2*)(qp0 + 16 * ks + 2 * t);
        float2 f1 = *(const float2*)(qp1 + 16 * ks + 2 * t);
        float2 f2 = *(const float2*)(qp0 + 16 * ks + 8 + 2 * t);
        float2 f3 = *(const float2*)(qp1 + 16 * ks + 8 + 2 * t);
        qa[ks].x = pack_h2(f0.x, f0.y);
        qa[ks].y = pack_h2(f1.x, f1.y);
        qa[ks].z = pack_h2(f2.x, f2.y);
        qa[ks].w = pack_h2(f3.x, f3.y);
    }

    float oacc[8][4];
#pragma unroll
    for (int nb = 0; nb < 8; nb++)
#pragma unroll
        for (int e = 0; e < 4; e++) oacc[nb][e] = 0.0f;
    float m0 = -1e30f, m1 = -1e30f, l0 = 0.0f, l1 = 0.0f;

    int ntiles = qt0 / 64 + 1;
    for (int kt = 0; kt < ntiles; kt++) {
        int s0 = kt * 64;

        // --- load K tile (fragment-native: u32 = K[s][2d],K[s][2d+1]) ---
        {
            const float* kp = k + base + (size_t)s0 * EE;
#pragma unroll
            for (int it = 0; it < 8; it++) {
                int tau = tid + it * 128;        // 0..1023
                int s = tau >> 4, j = tau & 15;  // j: float4 index over d
                float4 f = *(const float4*)(kp + (size_t)s * EE + 4 * j);
                int gg = s & 7, nb = s >> 3;
                int dp0 = 2 * j, dp1 = 2 * j + 1;
                int ks0 = dp0 >> 3, r0 = dp0 & 7;
                int ks1 = dp1 >> 3, r1 = dp1 & 7;
                Ks[((nb * 4 + ks0) * 32 + gg * 4 + (r0 & 3)) * 2 + (r0 >> 2)] = pack_h2(f.x, f.y);
                Ks[((nb * 4 + ks1) * 32 + gg * 4 + (r1 & 3)) * 2 + (r1 >> 2)] = pack_h2(f.z, f.w);
            }
            // --- load V tile (u32 = V[s][d],V[s+1][d] vertical pairs) ---
            const float* vp = v + base + (size_t)s0 * EE;
#pragma unroll
            for (int it = 0; it < 4; it++) {
                int tau = tid + it * 128;        // 0..511
                int sp = tau >> 4, dq = tau & 15;
                float4 a = *(const float4*)(vp + (size_t)(2 * sp) * EE + 4 * dq);
                float4 c = *(const float4*)(vp + (size_t)(2 * sp + 1) * EE + 4 * dq);
                int ks = sp >> 3, r = sp & 7;
                int reg = r >> 2, tt = r & 3;
                const float* al = &a.x;
                const float* cl = &c.x;
#pragma unroll
                for (int jj = 0; jj < 4; jj++) {
                    int d = 4 * dq + jj;
                    int nb = d >> 3, gg = d & 7;
                    Vs[((nb * 4 + ks) * 32 + gg * 4 + tt) * 2 + reg] = pack_h2(al[jj], cl[jj]);
                }
            }
        }
        __syncthreads();

        // --- S = Q K^T ---
        float sc[8][4];
#pragma unroll
        for (int nb = 0; nb < 8; nb++)
#pragma unroll
            for (int e = 0; e < 4; e++) sc[nb][e] = 0.0f;
#pragma unroll
        for (int ks = 0; ks < 4; ks++)
#pragma unroll
            for (int nb = 0; nb < 8; nb++) {
                uint2 bf = *(const uint2*)&Ks[((nb * 4 + ks) * 32 + lane) * 2];
                mma_f16(sc[nb], qa[ks], bf);
            }

        // --- causal mask (diagonal tile only) ---
        if (s0 == qt0) {
            int r0g = qrow0, r1g = qrow0 + 8;
#pragma unroll
            for (int nb = 0; nb < 8; nb++) {
                int scol = s0 + 8 * nb + 2 * t;
                if (scol > r0g)     sc[nb][0] = -1e30f;
                if (scol + 1 > r0g) sc[nb][1] = -1e30f;
                if (scol > r1g)     sc[nb][2] = -1e30f;
                if (scol + 1 > r1g) sc[nb][3] = -1e30f;
            }
        }

        // --- online softmax (fp32) ---
        float mx0 = -1e30f, mx1 = -1e30f;
#pragma unroll
        for (int nb = 0; nb < 8; nb++) {
            mx0 = fmaxf(mx0, fmaxf(sc[nb][0], sc[nb][1]));
            mx1 = fmaxf(mx1, fmaxf(sc[nb][2], sc[nb][3]));
        }
        mx0 = fmaxf(mx0, __shfl_xor_sync(0xffffffffu, mx0, 1));
        mx0 = fmaxf(mx0, __shfl_xor_sync(0xffffffffu, mx0, 2));
        mx1 = fmaxf(mx1, __shfl_xor_sync(0xffffffffu, mx1, 1));
        mx1 = fmaxf(mx1, __shfl_xor_sync(0xffffffffu, mx1, 2));
        float nm0 = fmaxf(m0, mx0), nm1 = fmaxf(m1, mx1);
        float a0 = __expf(m0 - nm0), a1 = __expf(m1 - nm1);

        uint32_t ph[8][2];
        float s0sum = 0.0f, s1sum = 0.0f;
#pragma unroll
        for (int nb = 0; nb < 8; nb++) {
            float e00 = __expf(sc[nb][0] - nm0);
            float e01 = __expf(sc[nb][1] - nm0);
            float e10 = __expf(sc[nb][2] - nm1);
            float e11 = __expf(sc[nb][3] - nm1);
            ph[nb][0] = pack_h2(e00, e01);
            ph[nb][1] = pack_h2(e10, e11);
            s0sum += e00 + e01;
            s1sum += e10 + e11;
        }
        s0sum += __shfl_xor_sync(0xffffffffu, s0sum, 1);
        s0sum += __shfl_xor_sync(0xffffffffu, s0sum, 2);
        s1sum += __shfl_xor_sync(0xffffffffu, s1sum, 1);
        s1sum += __shfl_xor_sync(0xffffffffu, s1sum, 2);
        l0 = l0 * a0 + s0sum;
        l1 = l1 * a1 + s1sum;
        m0 = nm0; m1 = nm1;

        // --- rescale O, then O += P V ---
#pragma unroll
        for (int nb = 0; nb < 8; nb++) {
            oacc[nb][0] *= a0; oacc[nb][1] *= a0;
            oacc[nb][2] *= a1; oacc[nb][3] *= a1;
        }
#pragma unroll
        for (int ks = 0; ks < 4; ks++) {
            uint4 pa;
            pa.x = ph[2 * ks][0];     // (g,   s 16ks+2t..)
            pa.y = ph[2 * ks][1];     // (g+8, s 16ks+2t..)
            pa.z = ph[2 * ks + 1][0]; // (g,   s 16ks+8+2t..)
            pa.w = ph[2 * ks + 1][1]; // (g+8, s 16ks+8+2t..)
#pragma unroll
            for (int nb = 0; nb < 8; nb++) {
                uint2 bf = *(const uint2*)&Vs[((nb * 4 + ks) * 32 + lane) * 2];
                mma_f16(oacc[nb], pa, bf);
            }
        }
        __syncthreads();
    }

    // --- write O (scale-after-softmax quirk: /l * 0.125) ---
    float inv0 = 0.125f / l0, inv1 = 0.125f / l1;
    float* op0 = o + base + (size_t)qrow0 * EE;
    float* op1 = op0 + (size_t)8 * EE;
#pragma unroll
    for (int nb = 0; nb < 8; nb++) {
        int d = 8 * nb + 2 * t;
        *(float2*)(op0 + d) = make_float2(oacc[nb][0] * inv0, oacc[nb][1] * inv0);
        *(float2*)(op1 + d) = make_float2(oacc[nb][2] * inv1, oacc[nb][3] * inv1);
    }
}

// ---------------- combine LSE partials + per-row loss term --------------------
__global__ __launch_bounds__(128) void lse_combine(const float2* __restrict__ part,
                                                   const float* __restrict__ logits,
                                                   const int* __restrict__ targets,
                                                   float* __restrict__ lterms) {
    int r = blockIdx.x * 4 + (threadIdx.x >> 5);
    int lane = threadIdx.x & 31;
    const float2* pr = part + (size_t)r * NBL;

    float M = -1e30f, L = 0.0f;
    for (int j = lane; j < NBL; j += 32) {
        float2 p = pr[j];
        float nm = fmaxf(M, p.x);
        L = L * __expf(M - nm) + p.y * __expf(p.x - nm);
        M = nm;
    }
#pragma unroll
    for (int off = 16; off; off >>= 1) {
        float Mo = __shfl_xor_sync(0xffffffffu, M, off);
        float Lo = __shfl_xor_sync(0xffffffffu, L, off);
        float nm = fmaxf(M, Mo);
        L = L * __expf(M - nm) + Lo * __expf(Mo - nm);
        M = nm;
    }
    if (lane == 0) {
        float lse = M + logf(L);
        lterms[r] = lse - __ldg(&logits[(size_t)r * VV + targets[r]]);
    }
}

__global__ __launch_bounds__(256) void loss_reduce(const float* __restrict__ lterms,
                                                   float* __restrict__ out, int do_write) {
    __shared__ float s[256];
    float acc = 0.0f;
    for (int i = threadIdx.x; i < BT; i += 256) acc += lterms[i];
    s[threadIdx.x] = acc;
    __syncthreads();
    for (int st = 128; st; st >>= 1) {
        if (threadIdx.x < (unsigned)st) s[threadIdx.x] += s[threadIdx.x + st];
        __syncthreads();
    }
    if (threadIdx.x == 0 && do_write) out[0] = s[0] / (float)BT;
}

// ------------------------------- launch ---------------------------------------
#define GSM_BYTES (4 * GM_BUF * sizeof(uint32_t))   // 32KB dynamic smem

extern "C" void kernel_launch(void* const* d_in, const int* in_sizes, int n_in,
                              void* d_out, int out_size) {
    const int*   tokens    = (const int*)d_in[0];
    const int*   targets   = (const int*)d_in[1];
    const float* tok_table = (const float*)d_in[2];
    const float* pos_emb   = (const float*)d_in[3];
    const float* Wq        = (const float*)d_in[4];
    const float* bq        = (const float*)d_in[5];
    const float* Wk        = (const float*)d_in[6];
    const float* bk        = (const float*)d_in[7];
    const float* Wv        = (const float*)d_in[8];
    const float* bv        = (const float*)d_in[9];
    const float* Wo        = (const float*)d_in[10];
    const float* bo        = (const float*)d_in[11];
    float* out = (float*)d_out;

    float *x, *q, *k, *v, *o, *lt;
    float2* lsep;
    cudaGetSymbolAddress((void**)&x,    g_x);
    cudaGetSymbolAddress((void**)&q,    g_q);
    cudaGetSymbolAddress((void**)&k,    g_k);
    cudaGetSymbolAddress((void**)&v,    g_v);
    cudaGetSymbolAddress((void**)&o,    g_o);
    cudaGetSymbolAddress((void**)&lt,   g_lterms);
    cudaGetSymbolAddress((void**)&lsep, g_lsep);

    static int smem_set = 0;
    if (!smem_set) {
        cudaFuncSetAttribute(gemm_mma, cudaFuncAttributeMaxDynamicSharedMemorySize,
                             (int)GSM_BYTES);
        smem_set = 1;
    }

    // 1) embedding
    embed_kernel<<<(BT * EE) / 256, 256>>>(tokens, tok_table, pos_emb, x);

    // 2) QKV projections
    dim3 gqkv(BT / GM_BM, EE / GM_BN);   // m fastest
    gemm_mma<<<gqkv, 256, GSM_BYTES>>>(x, Wq, bq, q, BT, EE, EE, nullptr);
    gemm_mma<<<gqkv, 256, GSM_BYTES>>>(x, Wk, bk, k, BT, EE, EE, nullptr);
    gemm_mma<<<gqkv, 256, GSM_BYTES>>>(x, Wv, bv, v, BT, EE, EE, nullptr);

    // 3) causal attention (tensor cores)
    attn_mma<<<dim3(TT / 64, HH, BB), 128>>>(q, k, v, o);

    // 4) output projection -> logits into d_out, with fused LSE partials
    dim3 glog(BT / GM_BM, VV / GM_BN);   // m fastest: Wo tile stays L2-resident
    gemm_mma<<<glog, 256, GSM_BYTES>>>(o, Wo, bo, out, BT, VV, EE, lsep);

    // 5) loss: combine partials, then reduce
    lse_combine<<<BT / 4, 128>>>(lsep, out, targets, lt);
    int write_loss = (out_size > BT * VV) ? 1 : 0;
    loss_reduce<<<1, 256>>>(lt, out + (size_t)BT * VV, write_loss);
}